// round 6
// baseline (speedup 1.0000x reference)
#include <cuda_runtime.h>
#include <math.h>
#include <stdint.h>

#define BB 4
#define LL 1024
#define EE 768
#define HH 12
#define DD 64
#define HALF 512
#define FF 3072
#define MTOT (BB*LL)   // 4096

// ---------------- scratch (no allocations allowed) ----------------
__device__ float g_sn [MTOT*EE];
__device__ float g_xn [MTOT*EE];
__device__ float g_q  [MTOT*EE];
__device__ float g_k  [MTOT*EE];
__device__ float g_v  [MTOT*EE];
__device__ float g_y  [MTOT*EE];
__device__ float g_x1 [MTOT*EE];
__device__ float g_xn2[MTOT*EE];
__device__ float g_h  [MTOT*FF];
__device__ int   g_gidx[MTOT];
__device__ int   g_cnt [MTOT];
// rounded weights
__device__ float g_wq [EE*EE];
__device__ float g_wk [EE*EE];
__device__ float g_wv [EE*EE];
__device__ float g_wc [EE*EE];
__device__ float g_wfc[FF*EE];
__device__ float g_wp [EE*FF];

// round-to-nearest tf32
__device__ __forceinline__ float rtf32(float x) {
    uint32_t u;
    asm("cvt.rna.tf32.f32 %0, %1;" : "=r"(u) : "f"(x));
    return __uint_as_float(u);
}

// ---------------- weight pre-rounding ----------------
__global__ void round_w_kernel(const float* __restrict__ src,
                               float* __restrict__ dst, int n4) {
    int i = blockIdx.x * blockDim.x + threadIdx.x;
    if (i < n4) {
        float4 v = ((const float4*)src)[i];
        v.x = rtf32(v.x); v.y = rtf32(v.y);
        v.z = rtf32(v.z); v.w = rtf32(v.w);
        ((float4*)dst)[i] = v;
    }
}

// ---------------- fuse-embed index scan ----------------
__global__ void fuse_idx_kernel(const int* __restrict__ mod_idx) {
    __shared__ int sbuf[1024];
    int b = blockIdx.x, j = threadIdx.x;
    int v = mod_idx[b*LL + j];
    int is2 = (v == 2) ? 1 : 0;
    sbuf[j] = is2;
    __syncthreads();
    #pragma unroll
    for (int off = 1; off < 1024; off <<= 1) {
        int t = (j >= off) ? sbuf[j - off] : 0;
        __syncthreads();
        sbuf[j] += t;
        __syncthreads();
    }
    int p2  = sbuf[j];
    int occ = is2 ? (p2 - 1) : (j - p2);
    occ = min(max(occ, 0), HALF - 1);
    g_gidx[b*LL + j] = b*HALF + occ;
}

// ---------------- prefix-length (mask) kernel ----------------
__global__ void cnt_kernel(const float* __restrict__ age,
                           const float* __restrict__ mod_age) {
    int b = blockIdx.x, q = threadIdx.x;
    float a = age[b*LL + q];
    const float* ma = mod_age + b*LL;
    int lo = 0, hi = LL;
    while (lo < hi) {
        int mid = (lo + hi) >> 1;
        if (ma[mid] <= a) lo = mid + 1; else hi = mid;
    }
    g_cnt[b*LL + q] = lo;
}

// ---------------- LayerNorm helper (dst rounded to tf32) ----------------
__device__ __forceinline__ void ln_row(const float* __restrict__ src,
                                       const float* __restrict__ w,
                                       const float* __restrict__ bia,
                                       float* __restrict__ dst) {
    int t = threadIdx.x;
    float v0 = src[t], v1 = src[t + 256], v2 = src[t + 512];
    float s  = v0 + v1 + v2;
    float ss = fmaf(v0, v0, fmaf(v1, v1, v2 * v2));
    __shared__ float red[16];
    #pragma unroll
    for (int o = 16; o; o >>= 1) {
        s  += __shfl_xor_sync(0xffffffffu, s,  o);
        ss += __shfl_xor_sync(0xffffffffu, ss, o);
    }
    int wi = t >> 5;
    if ((t & 31) == 0) { red[wi] = s; red[8 + wi] = ss; }
    __syncthreads();
    if (t == 0) {
        float ts = 0.f, tss = 0.f;
        #pragma unroll
        for (int i = 0; i < 8; i++) { ts += red[i]; tss += red[8 + i]; }
        float mean = ts * (1.0f / 768.0f);
        float var  = tss * (1.0f / 768.0f) - mean * mean;
        red[0] = mean;
        red[1] = rsqrtf(var + 1e-5f);
    }
    __syncthreads();
    float mean = red[0], inv = red[1];
    dst[t]       = rtf32((v0 - mean) * inv * w[t]       + bia[t]);
    dst[t + 256] = rtf32((v1 - mean) * inv * w[t + 256] + bia[t + 256]);
    dst[t + 512] = rtf32((v2 - mean) * inv * w[t + 512] + bia[t + 512]);
}

__global__ void ln_kernel(const float* __restrict__ src,
                          const float* __restrict__ w,
                          const float* __restrict__ bia,
                          float* __restrict__ dst) {
    int row = blockIdx.x;
    ln_row(src + (size_t)row * EE, w, bia, dst + (size_t)row * EE);
}

__global__ void gather_ln_kernel(const int* __restrict__ mod_idx,
                                 const float* __restrict__ e2,
                                 const float* __restrict__ e3,
                                 const float* __restrict__ w,
                                 const float* __restrict__ bia,
                                 float* __restrict__ dst) {
    int row = blockIdx.x;
    int sel = mod_idx[row];
    const float* src = ((sel == 2) ? e2 : e3) + (size_t)g_gidx[row] * EE;
    ln_row(src, w, bia, dst + (size_t)row * EE);
}

// =====================================================================
// mma.sync tf32 GEMM body: C[M,N] = A[M,K] @ W[N,K]^T (+bias, +res/GELU)
// CTA 128x128, 4 warps (warp tile 64x64), K-chunk 32, 2-stage cp.async,
// 2 CTAs per SM. smem rows padded to stride 36 (conflict-free frags).
// =====================================================================
__device__ __forceinline__ float gelu_exact(float x) {
    return 0.5f * x * (1.0f + erff(x * 0.70710678118654752440f));
}

#define NSTAGE 2
#define LDK 36
#define STG_FLOATS (2 * 128 * LDK)            // A + B per stage (9216 floats)
#define GEMM_SMEM (NSTAGE * STG_FLOATS * 4)   // 73728 bytes
#define GTHREADS 128

__device__ __forceinline__ void cp16(uint32_t dst, const void* src) {
    asm volatile("cp.async.cg.shared.global [%0], [%1], 16;" :: "r"(dst), "l"(src));
}

__device__ __forceinline__ void load_tile(const float* __restrict__ A,
                                          const float* __restrict__ W,
                                          int K, int tM, int tN, int k0,
                                          uint32_t sA, int tid) {
    uint32_t sB = sA + 128 * LDK * 4;
    #pragma unroll
    for (int j = 0; j < 8; j++) {
        int idx = tid + j * GTHREADS;
        int row = idx >> 3, c4 = idx & 7;
        uint32_t off = (uint32_t)(row * LDK + c4 * 4) * 4;
        cp16(sA + off, A + (size_t)(tM + row) * K + k0 + c4 * 4);
        cp16(sB + off, W + (size_t)(tN + row) * K + k0 + c4 * 4);
    }
}

template <int EPI>  // 0=bias, 1=bias+residual, 2=bias+GELU(rounded)
__device__ __forceinline__ void gemm_body(const float* __restrict__ A,
                                          const float* __restrict__ W,
                                          const float* __restrict__ bias,
                                          const float* __restrict__ R,
                                          float* __restrict__ C,
                                          int K, int N, int tM, int tN) {
    extern __shared__ __align__(16) float smem[];
    uint32_t smem_b = (uint32_t)__cvta_generic_to_shared(smem);
    int tid = threadIdx.x, wid = tid >> 5, lane = tid & 31;
    int wm = wid & 1, wn = wid >> 1;           // 2x2 warp grid, tile 64x64
    int gid = lane >> 2, tig = lane & 3;

    const int iters = K >> 5;

    float acc[4][8][4];
    #pragma unroll
    for (int mi = 0; mi < 4; mi++)
        #pragma unroll
        for (int ni = 0; ni < 8; ni++)
            #pragma unroll
            for (int r = 0; r < 4; r++) acc[mi][ni][r] = 0.f;

    load_tile(A, W, K, tM, tN, 0, smem_b, tid);
    asm volatile("cp.async.commit_group;" ::: "memory");

    for (int i = 0; i < iters; i++) {
        int li = i + 1;
        if (li < iters)
            load_tile(A, W, K, tM, tN, li * 32,
                      smem_b + (li & 1) * STG_FLOATS * 4, tid);
        asm volatile("cp.async.commit_group;" ::: "memory");
        asm volatile("cp.async.wait_group 1;" ::: "memory");
        __syncthreads();

        const float* As = smem + (i & 1) * STG_FLOATS;
        const float* Bs = As + 128 * LDK;
        const float* Ap = As + (wm * 64 + gid) * LDK + tig;
        const float* Bp = Bs + (wn * 64 + gid) * LDK + tig;

        #pragma unroll
        for (int ks = 0; ks < 4; ks++) {
            int kc = ks * 8;
            uint32_t a[4][4], b[8][2];
            #pragma unroll
            for (int mi = 0; mi < 4; mi++) {
                const float* p = Ap + mi * 16 * LDK + kc;
                a[mi][0] = __float_as_uint(p[0]);
                a[mi][1] = __float_as_uint(p[8 * LDK]);
                a[mi][2] = __float_as_uint(p[4]);
                a[mi][3] = __float_as_uint(p[8 * LDK + 4]);
            }
            #pragma unroll
            for (int ni = 0; ni < 8; ni++) {
                const float* p = Bp + ni * 8 * LDK + kc;
                b[ni][0] = __float_as_uint(p[0]);
                b[ni][1] = __float_as_uint(p[4]);
            }
            #pragma unroll
            for (int mi = 0; mi < 4; mi++)
                #pragma unroll
                for (int ni = 0; ni < 8; ni++)
                    asm volatile(
                        "mma.sync.aligned.m16n8k8.row.col.f32.tf32.tf32.f32 "
                        "{%0,%1,%2,%3}, {%4,%5,%6,%7}, {%8,%9}, {%0,%1,%2,%3};"
                        : "+f"(acc[mi][ni][0]), "+f"(acc[mi][ni][1]),
                          "+f"(acc[mi][ni][2]), "+f"(acc[mi][ni][3])
                        : "r"(a[mi][0]), "r"(a[mi][1]), "r"(a[mi][2]), "r"(a[mi][3]),
                          "r"(b[ni][0]), "r"(b[ni][1]));
        }
        __syncthreads();
    }

    #pragma unroll
    for (int mi = 0; mi < 4; mi++) {
        int r0 = tM + wm * 64 + mi * 16 + gid;
        #pragma unroll
        for (int ni = 0; ni < 8; ni++) {
            int c = tN + wn * 64 + ni * 8 + tig * 2;
            float bx = bias[c], by = bias[c + 1];
            float2 v0 = make_float2(acc[mi][ni][0] + bx, acc[mi][ni][1] + by);
            float2 v1 = make_float2(acc[mi][ni][2] + bx, acc[mi][ni][3] + by);
            size_t o0 = (size_t)r0 * N + c;
            size_t o1 = (size_t)(r0 + 8) * N + c;
            if (EPI == 1) {
                float2 rr0 = *(const float2*)(R + o0);
                float2 rr1 = *(const float2*)(R + o1);
                v0.x += rr0.x; v0.y += rr0.y;
                v1.x += rr1.x; v1.y += rr1.y;
            }
            if (EPI == 2) {
                v0.x = rtf32(gelu_exact(v0.x)); v0.y = rtf32(gelu_exact(v0.y));
                v1.x = rtf32(gelu_exact(v1.x)); v1.y = rtf32(gelu_exact(v1.y));
            }
            *(float2*)(C + o0) = v0;
            *(float2*)(C + o1) = v1;
        }
    }
}

template <int EPI>
__global__ __launch_bounds__(GTHREADS, 2)
void tc_gemm(const float* __restrict__ A, const float* __restrict__ W,
             const float* __restrict__ bias, const float* __restrict__ R,
             float* __restrict__ C, int K, int N) {
    gemm_body<EPI>(A, W, bias, R, C, K, N, blockIdx.y * 128, blockIdx.x * 128);
}

// fused QKV: blockIdx.x in [0,18): 0-5 Q, 6-11 K, 12-17 V
__global__ __launch_bounds__(GTHREADS, 2)
void qkv_gemm(const float* __restrict__ xn, const float* __restrict__ sn,
              const float* __restrict__ qb, const float* __restrict__ kb,
              const float* __restrict__ vb) {
    int part = blockIdx.x / 6;
    int bx   = blockIdx.x % 6;
    const float* A    = (part == 0) ? xn   : sn;
    const float* W    = (part == 0) ? g_wq : (part == 1) ? g_wk : g_wv;
    const float* bias = (part == 0) ? qb   : (part == 1) ? kb   : vb;
    float* C          = (part == 0) ? g_q  : (part == 1) ? g_k  : g_v;
    gemm_body<0>(A, W, bias, nullptr, C, EE, EE, blockIdx.y * 128, bx * 128);
}

// ---------------- prefix-masked flash attention (SIMT fp32) ----------------
__global__ __launch_bounds__(128)
void attn_kernel() {
    int bh = blockIdx.y;
    int b = bh / HH, h = bh - b * HH;
    int qrow = blockIdx.x * 128 + threadIdx.x;
    int gq = b * LL + qrow;

    float qr[DD];
    const float* Qp = g_q + (size_t)gq * EE + h * DD;
    #pragma unroll
    for (int d = 0; d < DD; d++) qr[d] = Qp[d] * 0.125f;

    int cq = g_cnt[gq];
    int kmax = g_cnt[b * LL + blockIdx.x * 128 + 127];

    __shared__ __align__(16) float Ks[32][DD];
    __shared__ __align__(16) float Vs[32][DD];

    float m = -INFINITY, l = 0.f;
    float acc[DD];
    #pragma unroll
    for (int d = 0; d < DD; d++) acc[d] = 0.f;

    for (int k0 = 0; k0 < kmax; k0 += 32) {
        for (int idx = threadIdx.x; idx < 32 * 16; idx += 128) {
            int r = idx >> 4, c4 = (idx & 15) << 2;
            int kg = k0 + r;
            float4 kv, vv;
            if (kg < kmax) {
                size_t off = ((size_t)(b * LL + kg)) * EE + h * DD + c4;
                kv = *(const float4*)(g_k + off);
                vv = *(const float4*)(g_v + off);
            } else {
                kv = make_float4(0.f, 0.f, 0.f, 0.f);
                vv = kv;
            }
            *(float4*)&Ks[r][c4] = kv;
            *(float4*)&Vs[r][c4] = vv;
        }
        __syncthreads();

        float s[32];
        float tmax = -INFINITY;
        int jlim = cq - k0;
        #pragma unroll 4
        for (int j = 0; j < 32; j++) {
            float dot = 0.f;
            const float4* kr = (const float4*)Ks[j];
            #pragma unroll
            for (int i = 0; i < 16; i++) {
                float4 kv = kr[i];
                dot = fmaf(qr[4*i+0], kv.x, dot);
                dot = fmaf(qr[4*i+1], kv.y, dot);
                dot = fmaf(qr[4*i+2], kv.z, dot);
                dot = fmaf(qr[4*i+3], kv.w, dot);
            }
            s[j] = (j < jlim) ? dot : -INFINITY;
            tmax = fmaxf(tmax, s[j]);
        }
        if (tmax > -INFINITY) {
            float mnew = fmaxf(m, tmax);
            float corr = __expf(m - mnew);
            l *= corr;
            #pragma unroll
            for (int d = 0; d < DD; d++) acc[d] *= corr;
            #pragma unroll 4
            for (int j = 0; j < 32; j++) {
                float p = __expf(s[j] - mnew);
                l += p;
                const float4* vr = (const float4*)Vs[j];
                #pragma unroll
                for (int i = 0; i < 16; i++) {
                    float4 vv = vr[i];
                    acc[4*i+0] = fmaf(p, vv.x, acc[4*i+0]);
                    acc[4*i+1] = fmaf(p, vv.y, acc[4*i+1]);
                    acc[4*i+2] = fmaf(p, vv.z, acc[4*i+2]);
                    acc[4*i+3] = fmaf(p, vv.w, acc[4*i+3]);
                }
            }
            m = mnew;
        }
        __syncthreads();
    }
    float invl = (l > 0.f) ? (1.0f / l) : 0.f;
    float* Yp = g_y + (size_t)gq * EE + h * DD;
    #pragma unroll
    for (int d = 0; d < DD; d++) Yp[d] = rtf32(acc[d] * invl);
}

// ---------------- launch ----------------
extern "C" void kernel_launch(void* const* d_in, const int* in_sizes, int n_in,
                              void* d_out, int out_size) {
    const float* x       = (const float*)d_in[0];
    const float* age     = (const float*)d_in[1];
    const int*   mod_idx = (const int*)  d_in[2];
    const float* mod_age = (const float*)d_in[3];
    const float* e2      = (const float*)d_in[4];
    const float* e3      = (const float*)d_in[5];
    const float* ln0w = (const float*)d_in[6];
    const float* ln0b = (const float*)d_in[7];
    const float* ln1w = (const float*)d_in[8];
    const float* ln1b = (const float*)d_in[9];
    const float* ln2w = (const float*)d_in[10];
    const float* ln2b = (const float*)d_in[11];
    const float* qw = (const float*)d_in[12];
    const float* qb = (const float*)d_in[13];
    const float* kw = (const float*)d_in[14];
    const float* kb = (const float*)d_in[15];
    const float* vw = (const float*)d_in[16];
    const float* vb = (const float*)d_in[17];
    const float* cw = (const float*)d_in[18];
    const float* cb = (const float*)d_in[19];
    const float* fcw = (const float*)d_in[20];
    const float* fcb = (const float*)d_in[21];
    const float* pw  = (const float*)d_in[22];
    const float* pb  = (const float*)d_in[23];
    float* out = (float*)d_out;

    float *sn, *xn, *y, *x1, *xn2, *hbuf;
    float *wq, *wk, *wv, *wc, *wfc, *wp;
    cudaGetSymbolAddress((void**)&sn,  g_sn);
    cudaGetSymbolAddress((void**)&xn,  g_xn);
    cudaGetSymbolAddress((void**)&y,   g_y);
    cudaGetSymbolAddress((void**)&x1,  g_x1);
    cudaGetSymbolAddress((void**)&xn2, g_xn2);
    cudaGetSymbolAddress((void**)&hbuf, g_h);
    cudaGetSymbolAddress((void**)&wq,  g_wq);
    cudaGetSymbolAddress((void**)&wk,  g_wk);
    cudaGetSymbolAddress((void**)&wv,  g_wv);
    cudaGetSymbolAddress((void**)&wc,  g_wc);
    cudaGetSymbolAddress((void**)&wfc, g_wfc);
    cudaGetSymbolAddress((void**)&wp,  g_wp);

    cudaFuncSetAttribute(tc_gemm<1>, cudaFuncAttributeMaxDynamicSharedMemorySize, GEMM_SMEM);
    cudaFuncSetAttribute(tc_gemm<2>, cudaFuncAttributeMaxDynamicSharedMemorySize, GEMM_SMEM);
    cudaFuncSetAttribute(qkv_gemm,   cudaFuncAttributeMaxDynamicSharedMemorySize, GEMM_SMEM);

    // 0. round weights to tf32 (RN) once per call
    round_w_kernel<<<(EE*EE/4 + 255)/256, 256>>>(qw, wq, EE*EE/4);
    round_w_kernel<<<(EE*EE/4 + 255)/256, 256>>>(kw, wk, EE*EE/4);
    round_w_kernel<<<(EE*EE/4 + 255)/256, 256>>>(vw, wv, EE*EE/4);
    round_w_kernel<<<(EE*EE/4 + 255)/256, 256>>>(cw, wc, EE*EE/4);
    round_w_kernel<<<(FF*EE/4 + 255)/256, 256>>>(fcw, wfc, FF*EE/4);
    round_w_kernel<<<(EE*FF/4 + 255)/256, 256>>>(pw, wp, EE*FF/4);

    // 1. fuse-embed occurrence indices + mask prefix lengths
    fuse_idx_kernel<<<BB, 1024>>>(mod_idx);
    cnt_kernel<<<BB, 1024>>>(age, mod_age);

    // 2. LN0(gathered mod embeddings) -> sn ; LN1(x) -> xn   (tf32-rounded)
    gather_ln_kernel<<<MTOT, 256>>>(mod_idx, e2, e3, ln0w, ln0b, sn);
    ln_kernel<<<MTOT, 256>>>(x, ln1w, ln1b, xn);

    // 3. fused QKV projection
    qkv_gemm<<<dim3(18, 32), GTHREADS, GEMM_SMEM>>>(xn, sn, qb, kb, vb);

    // 4. prefix-masked flash attention -> y (tf32-rounded)
    attn_kernel<<<dim3(LL / 128, BB * HH), 128>>>();

    // 5. out projection + residual -> x1
    tc_gemm<1><<<dim3(6, 32), GTHREADS, GEMM_SMEM>>>(y, wc, cb, x, x1, EE, EE);

    // 6. LN2 -> xn2 ; MLP with GELU ; proj + residual -> out
    ln_kernel<<<MTOT, 256>>>(x1, ln2w, ln2b, xn2);
    tc_gemm<2><<<dim3(24, 32), GTHREADS, GEMM_SMEM>>>(xn2, wfc, fcb, nullptr, hbuf, EE, FF);
    tc_gemm<1><<<dim3(6, 32), GTHREADS, GEMM_SMEM>>>(hbuf, wp, pb, x1, out, FF, EE);
}

// round 7
// speedup vs baseline: 2.2823x; 2.2823x over previous
#include <cuda_runtime.h>
#include <cuda_fp16.h>
#include <math.h>
#include <stdint.h>

#define BB 4
#define LL 1024
#define EE 768
#define HH 12
#define DD 64
#define HALF 512
#define FF 3072
#define MTOT (BB*LL)   // 4096

// ---------------- scratch (no allocations allowed) ----------------
__device__ __half g_sn [MTOT*EE];
__device__ __half g_xn [MTOT*EE];
__device__ __half g_q  [MTOT*EE];
__device__ __half g_k  [MTOT*EE];
__device__ __half g_v  [MTOT*EE];
__device__ __half g_y  [MTOT*EE];
__device__ float  g_x1 [MTOT*EE];
__device__ __half g_xn2[MTOT*EE];
__device__ __half g_h  [MTOT*FF];
__device__ int    g_gidx[MTOT];
__device__ int    g_cnt [MTOT];
// fp16 weights
__device__ __half g_wq [EE*EE];
__device__ __half g_wk [EE*EE];
__device__ __half g_wv [EE*EE];
__device__ __half g_wc [EE*EE];
__device__ __half g_wfc[FF*EE];
__device__ __half g_wp [EE*FF];

// ---------------- fused weight conversion fp32 -> fp16 ----------------
__global__ void round_w_all(const float* __restrict__ qw, const float* __restrict__ kw,
                            const float* __restrict__ vw, const float* __restrict__ cw,
                            const float* __restrict__ fcw, const float* __restrict__ pw) {
    const int S  = EE*EE/4;    // 147456 float4 per square weight
    const int SF = FF*EE/4;    // 589824 float4 per MLP weight
    int i = blockIdx.x * blockDim.x + threadIdx.x;
    const float* src; __half* dst; int off;
    if      (i <     S)      { src = qw;  dst = g_wq;  off = i; }
    else if (i < 2*S)        { src = kw;  dst = g_wk;  off = i - S; }
    else if (i < 3*S)        { src = vw;  dst = g_wv;  off = i - 2*S; }
    else if (i < 4*S)        { src = cw;  dst = g_wc;  off = i - 3*S; }
    else if (i < 4*S + SF)   { src = fcw; dst = g_wfc; off = i - 4*S; }
    else if (i < 4*S + 2*SF) { src = pw;  dst = g_wp;  off = i - 4*S - SF; }
    else return;
    float4 v = ((const float4*)src)[off];
    __half2* d = (__half2*)(dst + (size_t)off * 4);
    d[0] = __floats2half2_rn(v.x, v.y);
    d[1] = __floats2half2_rn(v.z, v.w);
}

// ---------------- fuse-embed index scan ----------------
__global__ void fuse_idx_kernel(const int* __restrict__ mod_idx) {
    __shared__ int sbuf[1024];
    int b = blockIdx.x, j = threadIdx.x;
    int v = mod_idx[b*LL + j];
    int is2 = (v == 2) ? 1 : 0;
    sbuf[j] = is2;
    __syncthreads();
    #pragma unroll
    for (int off = 1; off < 1024; off <<= 1) {
        int t = (j >= off) ? sbuf[j - off] : 0;
        __syncthreads();
        sbuf[j] += t;
        __syncthreads();
    }
    int p2  = sbuf[j];
    int occ = is2 ? (p2 - 1) : (j - p2);
    occ = min(max(occ, 0), HALF - 1);
    g_gidx[b*LL + j] = b*HALF + occ;
}

// ---------------- prefix-length (mask) kernel ----------------
__global__ void cnt_kernel(const float* __restrict__ age,
                           const float* __restrict__ mod_age) {
    int b = blockIdx.x, q = threadIdx.x;
    float a = age[b*LL + q];
    const float* ma = mod_age + b*LL;
    int lo = 0, hi = LL;
    while (lo < hi) {
        int mid = (lo + hi) >> 1;
        if (ma[mid] <= a) lo = mid + 1; else hi = mid;
    }
    g_cnt[b*LL + q] = lo;
}

// ---------------- LayerNorm helper (fp32 in -> fp16 out) ----------------
__device__ __forceinline__ void ln_row(const float* __restrict__ src,
                                       const float* __restrict__ w,
                                       const float* __restrict__ bia,
                                       __half* __restrict__ dst) {
    int t = threadIdx.x;
    float v0 = src[t], v1 = src[t + 256], v2 = src[t + 512];
    float s  = v0 + v1 + v2;
    float ss = fmaf(v0, v0, fmaf(v1, v1, v2 * v2));
    __shared__ float red[16];
    #pragma unroll
    for (int o = 16; o; o >>= 1) {
        s  += __shfl_xor_sync(0xffffffffu, s,  o);
        ss += __shfl_xor_sync(0xffffffffu, ss, o);
    }
    int wi = t >> 5;
    if ((t & 31) == 0) { red[wi] = s; red[8 + wi] = ss; }
    __syncthreads();
    if (t == 0) {
        float ts = 0.f, tss = 0.f;
        #pragma unroll
        for (int i = 0; i < 8; i++) { ts += red[i]; tss += red[8 + i]; }
        float mean = ts * (1.0f / 768.0f);
        float var  = tss * (1.0f / 768.0f) - mean * mean;
        red[0] = mean;
        red[1] = rsqrtf(var + 1e-5f);
    }
    __syncthreads();
    float mean = red[0], inv = red[1];
    dst[t]       = __float2half_rn((v0 - mean) * inv * w[t]       + bia[t]);
    dst[t + 256] = __float2half_rn((v1 - mean) * inv * w[t + 256] + bia[t + 256]);
    dst[t + 512] = __float2half_rn((v2 - mean) * inv * w[t + 512] + bia[t + 512]);
}

__global__ void ln_kernel(const float* __restrict__ src,
                          const float* __restrict__ w,
                          const float* __restrict__ bia,
                          __half* __restrict__ dst) {
    int row = blockIdx.x;
    ln_row(src + (size_t)row * EE, w, bia, dst + (size_t)row * EE);
}

__global__ void gather_ln_kernel(const int* __restrict__ mod_idx,
                                 const float* __restrict__ e2,
                                 const float* __restrict__ e3,
                                 const float* __restrict__ w,
                                 const float* __restrict__ bia,
                                 __half* __restrict__ dst) {
    int row = blockIdx.x;
    int sel = mod_idx[row];
    const float* src = ((sel == 2) ? e2 : e3) + (size_t)g_gidx[row] * EE;
    ln_row(src, w, bia, dst + (size_t)row * EE);
}

// =====================================================================
// fp16 mma.sync GEMM: C[M,N] = A[M,K] @ W[N,K]^T (+bias, +res/GELU)
// CTA 128x128, 8 warps (warp tile 64x32), K-chunk 64 halves (128B rows),
// 2-stage cp.async, 2 CTAs/SM. XOR-swizzled smem + ldmatrix fragments.
// =====================================================================
__device__ __forceinline__ float gelu_exact(float x) {
    return 0.5f * x * (1.0f + erff(x * 0.70710678118654752440f));
}

#define NSTAGE 2
#define STG_BYTES (2*128*128)          // A 16KB + B 16KB
#define GEMM_SMEM (NSTAGE*STG_BYTES)   // 65536
#define GTHREADS 256

__device__ __forceinline__ void cp16(uint32_t dst, const void* src) {
    asm volatile("cp.async.cg.shared.global [%0], [%1], 16;" :: "r"(dst), "l"(src));
}

// rows: 128B each = 8 chunks of 16B; chunk c of row r stored at c^(r&7)
__device__ __forceinline__ void load_tile(const __half* __restrict__ A,
                                          const __half* __restrict__ W,
                                          int K, int tM, int tN, int k0,
                                          uint32_t sA, int tid) {
    uint32_t sB = sA + 128 * 128;
    #pragma unroll
    for (int j = 0; j < 4; j++) {
        int idx = tid + j * GTHREADS;
        int row = idx >> 3, c = idx & 7;
        uint32_t off = (uint32_t)(row * 128 + ((c ^ (row & 7)) << 4));
        cp16(sA + off, A + (size_t)(tM + row) * K + k0 + c * 8);
        cp16(sB + off, W + (size_t)(tN + row) * K + k0 + c * 8);
    }
}

__device__ __forceinline__ void ldsm4(uint32_t* r, uint32_t addr) {
    asm volatile("ldmatrix.sync.aligned.m8n8.x4.shared.b16 {%0,%1,%2,%3}, [%4];"
                 : "=r"(r[0]), "=r"(r[1]), "=r"(r[2]), "=r"(r[3]) : "r"(addr));
}
__device__ __forceinline__ void ldsm2(uint32_t* r, uint32_t addr) {
    asm volatile("ldmatrix.sync.aligned.m8n8.x2.shared.b16 {%0,%1}, [%2];"
                 : "=r"(r[0]), "=r"(r[1]) : "r"(addr));
}

template <int EPI, typename OT>  // 0=bias->half, 1=bias+residual->float, 2=bias+GELU->half
__device__ __forceinline__ void gemm_body(const __half* __restrict__ A,
                                          const __half* __restrict__ W,
                                          const float* __restrict__ bias,
                                          const float* __restrict__ R,
                                          OT* __restrict__ C,
                                          int K, int N, int tM, int tN) {
    extern __shared__ __align__(16) char smem[];
    uint32_t smem_b = (uint32_t)__cvta_generic_to_shared(smem);
    int tid = threadIdx.x, wid = tid >> 5, lane = tid & 31;
    int wm = wid & 1, wn = wid >> 1;           // 2x4 warp grid, tile 64x32
    int gid = lane >> 2, tig = lane & 3;

    const int iters = K >> 6;                  // 64 halves per chunk

    float acc[4][4][4];
    #pragma unroll
    for (int mi = 0; mi < 4; mi++)
        #pragma unroll
        for (int ni = 0; ni < 4; ni++)
            #pragma unroll
            for (int r = 0; r < 4; r++) acc[mi][ni][r] = 0.f;

    load_tile(A, W, K, tM, tN, 0, smem_b, tid);
    asm volatile("cp.async.commit_group;" ::: "memory");

    // precompute per-lane ldmatrix row/chunk components
    int a_row = wm * 64 + (lane & 15);
    int a_kc  = lane >> 4;                     // 0 or 1
    int b_row = wn * 32 + (lane & 7);
    int b_kc  = (lane >> 3) & 1;

    for (int i = 0; i < iters; i++) {
        int li = i + 1;
        if (li < iters)
            load_tile(A, W, K, tM, tN, li * 64,
                      smem_b + (li & 1) * STG_BYTES, tid);
        asm volatile("cp.async.commit_group;" ::: "memory");
        asm volatile("cp.async.wait_group 1;" ::: "memory");
        __syncthreads();

        uint32_t As = smem_b + (i & 1) * STG_BYTES;
        uint32_t Bs = As + 128 * 128;

        #pragma unroll
        for (int ks = 0; ks < 4; ks++) {
            uint32_t a[4][4], b[4][2];
            #pragma unroll
            for (int mi = 0; mi < 4; mi++) {
                int r = a_row + mi * 16;
                int kc = ks * 2 + a_kc;
                ldsm4(a[mi], As + r * 128 + ((kc ^ (r & 7)) << 4));
            }
            #pragma unroll
            for (int ni = 0; ni < 4; ni++) {
                int r = b_row + ni * 8;
                int kc = ks * 2 + b_kc;
                ldsm2(b[ni], Bs + r * 128 + ((kc ^ (r & 7)) << 4));
            }
            #pragma unroll
            for (int mi = 0; mi < 4; mi++)
                #pragma unroll
                for (int ni = 0; ni < 4; ni++)
                    asm volatile(
                        "mma.sync.aligned.m16n8k16.row.col.f32.f16.f16.f32 "
                        "{%0,%1,%2,%3}, {%4,%5,%6,%7}, {%8,%9}, {%0,%1,%2,%3};"
                        : "+f"(acc[mi][ni][0]), "+f"(acc[mi][ni][1]),
                          "+f"(acc[mi][ni][2]), "+f"(acc[mi][ni][3])
                        : "r"(a[mi][0]), "r"(a[mi][1]), "r"(a[mi][2]), "r"(a[mi][3]),
                          "r"(b[ni][0]), "r"(b[ni][1]));
        }
        __syncthreads();
    }

    // epilogue: d0,d1 @ (row=gid, col=2*tig+{0,1}), d2,d3 @ row+8
    #pragma unroll
    for (int mi = 0; mi < 4; mi++) {
        int r0 = tM + wm * 64 + mi * 16 + gid;
        #pragma unroll
        for (int ni = 0; ni < 4; ni++) {
            int c = tN + wn * 32 + ni * 8 + tig * 2;
            float bx = bias[c], by = bias[c + 1];
            float2 v0 = make_float2(acc[mi][ni][0] + bx, acc[mi][ni][1] + by);
            float2 v1 = make_float2(acc[mi][ni][2] + bx, acc[mi][ni][3] + by);
            size_t o0 = (size_t)r0 * N + c;
            size_t o1 = (size_t)(r0 + 8) * N + c;
            if (EPI == 1) {
                float2 rr0 = *(const float2*)(R + o0);
                float2 rr1 = *(const float2*)(R + o1);
                v0.x += rr0.x; v0.y += rr0.y;
                v1.x += rr1.x; v1.y += rr1.y;
                *(float2*)((float*)C + o0) = v0;
                *(float2*)((float*)C + o1) = v1;
            } else {
                if (EPI == 2) {
                    v0.x = gelu_exact(v0.x); v0.y = gelu_exact(v0.y);
                    v1.x = gelu_exact(v1.x); v1.y = gelu_exact(v1.y);
                }
                *(__half2*)((__half*)C + o0) = __floats2half2_rn(v0.x, v0.y);
                *(__half2*)((__half*)C + o1) = __floats2half2_rn(v1.x, v1.y);
            }
        }
    }
}

template <int EPI, typename OT>
__global__ __launch_bounds__(GTHREADS, 2)
void tc_gemm(const __half* __restrict__ A, const __half* __restrict__ W,
             const float* __restrict__ bias, const float* __restrict__ R,
             OT* __restrict__ C, int K, int N) {
    gemm_body<EPI, OT>(A, W, bias, R, C, K, N, blockIdx.y * 128, blockIdx.x * 128);
}

// fused QKV: blockIdx.x in [0,18): 0-5 Q, 6-11 K, 12-17 V
__global__ __launch_bounds__(GTHREADS, 2)
void qkv_gemm(const float* __restrict__ qb, const float* __restrict__ kb,
              const float* __restrict__ vb) {
    int part = blockIdx.x / 6;
    int bx   = blockIdx.x % 6;
    const __half* A    = (part == 0) ? g_xn : g_sn;
    const __half* W    = (part == 0) ? g_wq : (part == 1) ? g_wk : g_wv;
    const float* bias  = (part == 0) ? qb   : (part == 1) ? kb   : vb;
    __half* C          = (part == 0) ? g_q  : (part == 1) ? g_k  : g_v;
    gemm_body<0, __half>(A, W, bias, nullptr, C, EE, EE, blockIdx.y * 128, bx * 128);
}

// ---------------- prefix-masked flash attention (fp16 in, fp32 math) ------
__global__ __launch_bounds__(128)
void attn_kernel() {
    int bh = blockIdx.y;
    int b = bh / HH, h = bh - b * HH;
    int qrow = blockIdx.x * 128 + threadIdx.x;
    int gq = b * LL + qrow;

    float qr[DD];
    const __half* Qp = g_q + (size_t)gq * EE + h * DD;
    #pragma unroll
    for (int d = 0; d < DD; d += 2) {
        float2 qq = __half22float2(*(const __half2*)(Qp + d));
        qr[d] = qq.x * 0.125f; qr[d+1] = qq.y * 0.125f;
    }

    int cq = g_cnt[gq];
    int kmax = g_cnt[b * LL + blockIdx.x * 128 + 127];

    __shared__ __align__(16) float Ks[32][DD];
    __shared__ __align__(16) float Vs[32][DD];

    float m = -INFINITY, l = 0.f;
    float acc[DD];
    #pragma unroll
    for (int d = 0; d < DD; d++) acc[d] = 0.f;

    for (int k0 = 0; k0 < kmax; k0 += 32) {
        for (int idx = threadIdx.x; idx < 32 * 16; idx += 128) {
            int r = idx >> 4, c4 = (idx & 15) << 2;
            int kg = k0 + r;
            float4 kv = make_float4(0.f,0.f,0.f,0.f), vv = kv;
            if (kg < kmax) {
                size_t off = ((size_t)(b * LL + kg)) * EE + h * DD + c4;
                float2 klo = __half22float2(*(const __half2*)(g_k + off));
                float2 khi = __half22float2(*(const __half2*)(g_k + off + 2));
                float2 vlo = __half22float2(*(const __half2*)(g_v + off));
                float2 vhi = __half22float2(*(const __half2*)(g_v + off + 2));
                kv = make_float4(klo.x, klo.y, khi.x, khi.y);
                vv = make_float4(vlo.x, vlo.y, vhi.x, vhi.y);
            }
            *(float4*)&Ks[r][c4] = kv;
            *(float4*)&Vs[r][c4] = vv;
        }
        __syncthreads();

        float s[32];
        float tmax = -INFINITY;
        int jlim = cq - k0;
        #pragma unroll 4
        for (int j = 0; j < 32; j++) {
            float dot = 0.f;
            const float4* kr = (const float4*)Ks[j];
            #pragma unroll
            for (int i = 0; i < 16; i++) {
                float4 kv = kr[i];
                dot = fmaf(qr[4*i+0], kv.x, dot);
                dot = fmaf(qr[4*i+1], kv.y, dot);
                dot = fmaf(qr[4*i+2], kv.z, dot);
                dot = fmaf(qr[4*i+3], kv.w, dot);
            }
            s[j] = (j < jlim) ? dot : -INFINITY;
            tmax = fmaxf(tmax, s[j]);
        }
        if (tmax > -INFINITY) {
            float mnew = fmaxf(m, tmax);
            float corr = __expf(m - mnew);
            l *= corr;
            #pragma unroll
            for (int d = 0; d < DD; d++) acc[d] *= corr;
            #pragma unroll 4
            for (int j = 0; j < 32; j++) {
                float p = __expf(s[j] - mnew);
                l += p;
                const float4* vr = (const float4*)Vs[j];
                #pragma unroll
                for (int i = 0; i < 16; i++) {
                    float4 vv = vr[i];
                    acc[4*i+0] = fmaf(p, vv.x, acc[4*i+0]);
                    acc[4*i+1] = fmaf(p, vv.y, acc[4*i+1]);
                    acc[4*i+2] = fmaf(p, vv.z, acc[4*i+2]);
                    acc[4*i+3] = fmaf(p, vv.w, acc[4*i+3]);
                }
            }
            m = mnew;
        }
        __syncthreads();
    }
    float invl = (l > 0.f) ? (1.0f / l) : 0.f;
    __half* Yp = g_y + (size_t)gq * EE + h * DD;
    #pragma unroll
    for (int d = 0; d < DD; d += 2)
        *(__half2*)(Yp + d) = __floats2half2_rn(acc[d] * invl, acc[d+1] * invl);
}

// ---------------- launch ----------------
extern "C" void kernel_launch(void* const* d_in, const int* in_sizes, int n_in,
                              void* d_out, int out_size) {
    const float* x       = (const float*)d_in[0];
    const float* age     = (const float*)d_in[1];
    const int*   mod_idx = (const int*)  d_in[2];
    const float* mod_age = (const float*)d_in[3];
    const float* e2      = (const float*)d_in[4];
    const float* e3      = (const float*)d_in[5];
    const float* ln0w = (const float*)d_in[6];
    const float* ln0b = (const float*)d_in[7];
    const float* ln1w = (const float*)d_in[8];
    const float* ln1b = (const float*)d_in[9];
    const float* ln2w = (const float*)d_in[10];
    const float* ln2b = (const float*)d_in[11];
    const float* qw = (const float*)d_in[12];
    const float* qb = (const float*)d_in[13];
    const float* kw = (const float*)d_in[14];
    const float* kb = (const float*)d_in[15];
    const float* vw = (const float*)d_in[16];
    const float* vb = (const float*)d_in[17];
    const float* cw = (const float*)d_in[18];
    const float* cb = (const float*)d_in[19];
    const float* fcw = (const float*)d_in[20];
    const float* fcb = (const float*)d_in[21];
    const float* pw  = (const float*)d_in[22];
    const float* pb  = (const float*)d_in[23];
    float* out = (float*)d_out;

    __half *sn, *xn, *y, *xn2, *hbuf;
    __half *wc, *wfc, *wp;
    float *x1;
    cudaGetSymbolAddress((void**)&sn,  g_sn);
    cudaGetSymbolAddress((void**)&xn,  g_xn);
    cudaGetSymbolAddress((void**)&y,   g_y);
    cudaGetSymbolAddress((void**)&x1,  g_x1);
    cudaGetSymbolAddress((void**)&xn2, g_xn2);
    cudaGetSymbolAddress((void**)&hbuf, g_h);
    cudaGetSymbolAddress((void**)&wc,  g_wc);
    cudaGetSymbolAddress((void**)&wfc, g_wfc);
    cudaGetSymbolAddress((void**)&wp,  g_wp);

    cudaFuncSetAttribute((const void*)tc_gemm<1, float>,  cudaFuncAttributeMaxDynamicSharedMemorySize, GEMM_SMEM);
    cudaFuncSetAttribute((const void*)tc_gemm<2, __half>, cudaFuncAttributeMaxDynamicSharedMemorySize, GEMM_SMEM);
    cudaFuncSetAttribute((const void*)qkv_gemm,           cudaFuncAttributeMaxDynamicSharedMemorySize, GEMM_SMEM);

    // 0. convert all weights to fp16 in one launch
    {
        const int total = 4*(EE*EE/4) + 2*(FF*EE/4);
        round_w_all<<<(total + 255)/256, 256>>>(qw, kw, vw, cw, fcw, pw);
    }

    // 1. fuse-embed occurrence indices + mask prefix lengths
    fuse_idx_kernel<<<BB, 1024>>>(mod_idx);
    cnt_kernel<<<BB, 1024>>>(age, mod_age);

    // 2. LN0(gathered mod embeddings) -> sn ; LN1(x) -> xn   (fp16 out)
    gather_ln_kernel<<<MTOT, 256>>>(mod_idx, e2, e3, ln0w, ln0b, sn);
    ln_kernel<<<MTOT, 256>>>(x, ln1w, ln1b, xn);

    // 3. fused QKV projection (fp16 mma)
    qkv_gemm<<<dim3(18, 32), GTHREADS, GEMM_SMEM>>>(qb, kb, vb);

    // 4. prefix-masked flash attention -> y (fp16)
    attn_kernel<<<dim3(LL / 128, BB * HH), 128>>>();

    // 5. out projection + residual -> x1 (fp32)
    tc_gemm<1, float><<<dim3(6, 32), GTHREADS, GEMM_SMEM>>>(y, wc, cb, x, x1, EE, EE);

    // 6. LN2 -> xn2 ; MLP with GELU ; proj + residual -> out
    ln_kernel<<<MTOT, 256>>>(x1, ln2w, ln2b, xn2);
    tc_gemm<2, __half><<<dim3(24, 32), GTHREADS, GEMM_SMEM>>>(xn2, wfc, fcb, nullptr, hbuf, EE, FF);
    tc_gemm<1, float><<<dim3(6, 32), GTHREADS, GEMM_SMEM>>>(hbuf, wp, pb, x1, out, FF, EE);
}

// round 10
// speedup vs baseline: 3.3636x; 1.4738x over previous
#include <cuda_runtime.h>
#include <cuda_fp16.h>
#include <math.h>
#include <stdint.h>

#define BB 4
#define LL 1024
#define EE 768
#define HH 12
#define DD 64
#define HALF 512
#define FF 3072
#define MTOT (BB*LL)   // 4096

// ---------------- scratch (no allocations allowed) ----------------
__device__ __half g_sn [MTOT*EE];
__device__ __half g_xn [MTOT*EE];
__device__ __half g_q  [MTOT*EE];
__device__ __half g_k  [MTOT*EE];
__device__ __half g_v  [MTOT*EE];
__device__ __half g_y  [MTOT*EE];
__device__ float  g_x1 [MTOT*EE];
__device__ __half g_xn2[MTOT*EE];
__device__ __half g_h  [MTOT*FF];
__device__ int    g_gidx[MTOT];
__device__ int    g_cnt [MTOT];
// fp16 weights
__device__ __half g_wq [EE*EE];
__device__ __half g_wk [EE*EE];
__device__ __half g_wv [EE*EE];
__device__ __half g_wc [EE*EE];
__device__ __half g_wfc[FF*EE];
__device__ __half g_wp [EE*FF];

__device__ __forceinline__ uint32_t h2u(__half2 h) {
    return *reinterpret_cast<uint32_t*>(&h);
}

// ---------------- fused weight conversion fp32 -> fp16 ----------------
__global__ void round_w_all(const float* __restrict__ qw, const float* __restrict__ kw,
                            const float* __restrict__ vw, const float* __restrict__ cw,
                            const float* __restrict__ fcw, const float* __restrict__ pw) {
    const int S  = EE*EE/4;
    const int SF = FF*EE/4;
    int i = blockIdx.x * blockDim.x + threadIdx.x;
    const float* src; __half* dst; int off;
    if      (i <     S)      { src = qw;  dst = g_wq;  off = i; }
    else if (i < 2*S)        { src = kw;  dst = g_wk;  off = i - S; }
    else if (i < 3*S)        { src = vw;  dst = g_wv;  off = i - 2*S; }
    else if (i < 4*S)        { src = cw;  dst = g_wc;  off = i - 3*S; }
    else if (i < 4*S + SF)   { src = fcw; dst = g_wfc; off = i - 4*S; }
    else if (i < 4*S + 2*SF) { src = pw;  dst = g_wp;  off = i - 4*S - SF; }
    else return;
    float4 v = ((const float4*)src)[off];
    __half2* d = (__half2*)(dst + (size_t)off * 4);
    d[0] = __floats2half2_rn(v.x, v.y);
    d[1] = __floats2half2_rn(v.z, v.w);
}

// ---------------- fuse-embed index scan ----------------
__global__ void fuse_idx_kernel(const int* __restrict__ mod_idx) {
    __shared__ int sbuf[1024];
    int b = blockIdx.x, j = threadIdx.x;
    int v = mod_idx[b*LL + j];
    int is2 = (v == 2) ? 1 : 0;
    sbuf[j] = is2;
    __syncthreads();
    #pragma unroll
    for (int off = 1; off < 1024; off <<= 1) {
        int t = (j >= off) ? sbuf[j - off] : 0;
        __syncthreads();
        sbuf[j] += t;
        __syncthreads();
    }
    int p2  = sbuf[j];
    int occ = is2 ? (p2 - 1) : (j - p2);
    occ = min(max(occ, 0), HALF - 1);
    g_gidx[b*LL + j] = b*HALF + occ;
}

// ---------------- prefix-length (mask) kernel ----------------
__global__ void cnt_kernel(const float* __restrict__ age,
                           const float* __restrict__ mod_age) {
    int b = blockIdx.x, q = threadIdx.x;
    float a = age[b*LL + q];
    const float* ma = mod_age + b*LL;
    int lo = 0, hi = LL;
    while (lo < hi) {
        int mid = (lo + hi) >> 1;
        if (ma[mid] <= a) lo = mid + 1; else hi = mid;
    }
    g_cnt[b*LL + q] = lo;
}

// ---------------- LayerNorm helper (fp32 in -> fp16 out) ----------------
__device__ __forceinline__ void ln_row(const float* __restrict__ src,
                                       const float* __restrict__ w,
                                       const float* __restrict__ bia,
                                       __half* __restrict__ dst) {
    int t = threadIdx.x;
    float v0 = src[t], v1 = src[t + 256], v2 = src[t + 512];
    float s  = v0 + v1 + v2;
    float ss = fmaf(v0, v0, fmaf(v1, v1, v2 * v2));
    __shared__ float red[16];
    #pragma unroll
    for (int o = 16; o; o >>= 1) {
        s  += __shfl_xor_sync(0xffffffffu, s,  o);
        ss += __shfl_xor_sync(0xffffffffu, ss, o);
    }
    int wi = t >> 5;
    if ((t & 31) == 0) { red[wi] = s; red[8 + wi] = ss; }
    __syncthreads();
    if (t == 0) {
        float ts = 0.f, tss = 0.f;
        #pragma unroll
        for (int i = 0; i < 8; i++) { ts += red[i]; tss += red[8 + i]; }
        float mean = ts * (1.0f / 768.0f);
        float var  = tss * (1.0f / 768.0f) - mean * mean;
        red[0] = mean;
        red[1] = rsqrtf(var + 1e-5f);
    }
    __syncthreads();
    float mean = red[0], inv = red[1];
    dst[t]       = __float2half_rn((v0 - mean) * inv * w[t]       + bia[t]);
    dst[t + 256] = __float2half_rn((v1 - mean) * inv * w[t + 256] + bia[t + 256]);
    dst[t + 512] = __float2half_rn((v2 - mean) * inv * w[t + 512] + bia[t + 512]);
}

__global__ void ln_kernel(const float* __restrict__ src,
                          const float* __restrict__ w,
                          const float* __restrict__ bia,
                          __half* __restrict__ dst) {
    int row = blockIdx.x;
    ln_row(src + (size_t)row * EE, w, bia, dst + (size_t)row * EE);
}

__global__ void gather_ln_kernel(const int* __restrict__ mod_idx,
                                 const float* __restrict__ e2,
                                 const float* __restrict__ e3,
                                 const float* __restrict__ w,
                                 const float* __restrict__ bia,
                                 __half* __restrict__ dst) {
    int row = blockIdx.x;
    int sel = mod_idx[row];
    const float* src = ((sel == 2) ? e2 : e3) + (size_t)g_gidx[row] * EE;
    ln_row(src, w, bia, dst + (size_t)row * EE);
}

// =====================================================================
// shared mma helpers
// =====================================================================
__device__ __forceinline__ float gelu_exact(float x) {
    return 0.5f * x * (1.0f + erff(x * 0.70710678118654752440f));
}

__device__ __forceinline__ void cp16(uint32_t dst, const void* src) {
    asm volatile("cp.async.cg.shared.global [%0], [%1], 16;" :: "r"(dst), "l"(src));
}
__device__ __forceinline__ void ldsm4(uint32_t* r, uint32_t addr) {
    asm volatile("ldmatrix.sync.aligned.m8n8.x4.shared.b16 {%0,%1,%2,%3}, [%4];"
                 : "=r"(r[0]), "=r"(r[1]), "=r"(r[2]), "=r"(r[3]) : "r"(addr));
}
__device__ __forceinline__ void ldsm2(uint32_t* r, uint32_t addr) {
    asm volatile("ldmatrix.sync.aligned.m8n8.x2.shared.b16 {%0,%1}, [%2];"
                 : "=r"(r[0]), "=r"(r[1]) : "r"(addr));
}
__device__ __forceinline__ void ldsm2t(uint32_t* r, uint32_t addr) {
    asm volatile("ldmatrix.sync.aligned.m8n8.x2.trans.shared.b16 {%0,%1}, [%2];"
                 : "=r"(r[0]), "=r"(r[1]) : "r"(addr));
}
__device__ __forceinline__ void mma16816(float* c, const uint32_t* a, const uint32_t* b) {
    asm volatile(
        "mma.sync.aligned.m16n8k16.row.col.f32.f16.f16.f32 "
        "{%0,%1,%2,%3}, {%4,%5,%6,%7}, {%8,%9}, {%0,%1,%2,%3};"
        : "+f"(c[0]), "+f"(c[1]), "+f"(c[2]), "+f"(c[3])
        : "r"(a[0]), "r"(a[1]), "r"(a[2]), "r"(a[3]), "r"(b[0]), "r"(b[1]));
}

// =====================================================================
// fp16 mma GEMM: C[M,N] = A[M,K] @ W[N,K]^T (+bias, +res/GELU)
// =====================================================================
#define NSTAGE 2
#define STG_BYTES (2*128*128)
#define GEMM_SMEM (NSTAGE*STG_BYTES)
#define GTHREADS 256

__device__ __forceinline__ void load_tile(const __half* __restrict__ A,
                                          const __half* __restrict__ W,
                                          int K, int tM, int tN, int k0,
                                          uint32_t sA, int tid) {
    uint32_t sB = sA + 128 * 128;
    #pragma unroll
    for (int j = 0; j < 4; j++) {
        int idx = tid + j * GTHREADS;
        int row = idx >> 3, c = idx & 7;
        uint32_t off = (uint32_t)(row * 128 + ((c ^ (row & 7)) << 4));
        cp16(sA + off, A + (size_t)(tM + row) * K + k0 + c * 8);
        cp16(sB + off, W + (size_t)(tN + row) * K + k0 + c * 8);
    }
}

template <int EPI, typename OT>
__device__ __forceinline__ void gemm_body(const __half* __restrict__ A,
                                          const __half* __restrict__ W,
                                          const float* __restrict__ bias,
                                          const float* __restrict__ R,
                                          OT* __restrict__ C,
                                          int K, int N, int tM, int tN) {
    extern __shared__ __align__(16) char smem[];
    uint32_t smem_b = (uint32_t)__cvta_generic_to_shared(smem);
    int tid = threadIdx.x, wid = tid >> 5, lane = tid & 31;
    int wm = wid & 1, wn = wid >> 1;
    int gid = lane >> 2, tig = lane & 3;

    const int iters = K >> 6;

    float acc[4][4][4];
    #pragma unroll
    for (int mi = 0; mi < 4; mi++)
        #pragma unroll
        for (int ni = 0; ni < 4; ni++)
            #pragma unroll
            for (int r = 0; r < 4; r++) acc[mi][ni][r] = 0.f;

    load_tile(A, W, K, tM, tN, 0, smem_b, tid);
    asm volatile("cp.async.commit_group;" ::: "memory");

    int a_row = wm * 64 + (lane & 15);
    int a_kc  = lane >> 4;
    int b_row = wn * 32 + (lane & 7);
    int b_kc  = (lane >> 3) & 1;

    for (int i = 0; i < iters; i++) {
        int li = i + 1;
        if (li < iters)
            load_tile(A, W, K, tM, tN, li * 64,
                      smem_b + (li & 1) * STG_BYTES, tid);
        asm volatile("cp.async.commit_group;" ::: "memory");
        asm volatile("cp.async.wait_group 1;" ::: "memory");
        __syncthreads();

        uint32_t As = smem_b + (i & 1) * STG_BYTES;
        uint32_t Bs = As + 128 * 128;

        #pragma unroll
        for (int ks = 0; ks < 4; ks++) {
            uint32_t a[4][4], b[4][2];
            #pragma unroll
            for (int mi = 0; mi < 4; mi++) {
                int r = a_row + mi * 16;
                int kc = ks * 2 + a_kc;
                ldsm4(a[mi], As + r * 128 + ((kc ^ (r & 7)) << 4));
            }
            #pragma unroll
            for (int ni = 0; ni < 4; ni++) {
                int r = b_row + ni * 8;
                int kc = ks * 2 + b_kc;
                ldsm2(b[ni], Bs + r * 128 + ((kc ^ (r & 7)) << 4));
            }
            #pragma unroll
            for (int mi = 0; mi < 4; mi++)
                #pragma unroll
                for (int ni = 0; ni < 4; ni++)
                    mma16816(acc[mi][ni], a[mi], b[ni]);
        }
        __syncthreads();
    }

    #pragma unroll
    for (int mi = 0; mi < 4; mi++) {
        int r0 = tM + wm * 64 + mi * 16 + gid;
        #pragma unroll
        for (int ni = 0; ni < 4; ni++) {
            int c = tN + wn * 32 + ni * 8 + tig * 2;
            float bx = bias[c], by = bias[c + 1];
            float2 v0 = make_float2(acc[mi][ni][0] + bx, acc[mi][ni][1] + by);
            float2 v1 = make_float2(acc[mi][ni][2] + bx, acc[mi][ni][3] + by);
            size_t o0 = (size_t)r0 * N + c;
            size_t o1 = (size_t)(r0 + 8) * N + c;
            if (EPI == 1) {
                float2 rr0 = *(const float2*)(R + o0);
                float2 rr1 = *(const float2*)(R + o1);
                v0.x += rr0.x; v0.y += rr0.y;
                v1.x += rr1.x; v1.y += rr1.y;
                *(float2*)((float*)C + o0) = v0;
                *(float2*)((float*)C + o1) = v1;
            } else {
                if (EPI == 2) {
                    v0.x = gelu_exact(v0.x); v0.y = gelu_exact(v0.y);
                    v1.x = gelu_exact(v1.x); v1.y = gelu_exact(v1.y);
                }
                *(__half2*)((__half*)C + o0) = __floats2half2_rn(v0.x, v0.y);
                *(__half2*)((__half*)C + o1) = __floats2half2_rn(v1.x, v1.y);
            }
        }
    }
}

template <int EPI, typename OT>
__global__ __launch_bounds__(GTHREADS, 2)
void tc_gemm(const __half* __restrict__ A, const __half* __restrict__ W,
             const float* __restrict__ bias, const float* __restrict__ R,
             OT* __restrict__ C, int K, int N) {
    gemm_body<EPI, OT>(A, W, bias, R, C, K, N, blockIdx.y * 128, blockIdx.x * 128);
}

__global__ __launch_bounds__(GTHREADS, 2)
void qkv_gemm(const float* __restrict__ qb, const float* __restrict__ kb,
              const float* __restrict__ vb) {
    int part = blockIdx.x / 6;
    int bx   = blockIdx.x % 6;
    const __half* A    = (part == 0) ? g_xn : g_sn;
    const __half* W    = (part == 0) ? g_wq : (part == 1) ? g_wk : g_wv;
    const float* bias  = (part == 0) ? qb   : (part == 1) ? kb   : vb;
    __half* C          = (part == 0) ? g_q  : (part == 1) ? g_k  : g_v;
    gemm_body<0, __half>(A, W, bias, nullptr, C, EE, EE, blockIdx.y * 128, bx * 128);
}

// =====================================================================
// tensor-core prefix-masked flash attention
// CTA: 64 queries, 4 warps (16 q-rows each), K-tiles of 64, double buffer.
// =====================================================================
__global__ __launch_bounds__(128)
void attn_kernel() {
    __shared__ __align__(16) __half sQ[64 * 64];
    __shared__ __align__(16) __half sK[2][64 * 64];
    __shared__ __align__(16) __half sV[2][64 * 64];

    int bh = blockIdx.y, b = bh / HH, h = bh - b * HH;
    int qbase = blockIdx.x * 64;
    int tid = threadIdx.x, wid = tid >> 5, lane = tid & 31;
    int gid = lane >> 2, tig = lane & 3;

    uint32_t sQb = (uint32_t)__cvta_generic_to_shared(sQ);
    uint32_t sKb0 = (uint32_t)__cvta_generic_to_shared(sK[0]);
    uint32_t sKb1 = (uint32_t)__cvta_generic_to_shared(sK[1]);
    uint32_t sVb0 = (uint32_t)__cvta_generic_to_shared(sV[0]);
    uint32_t sVb1 = (uint32_t)__cvta_generic_to_shared(sV[1]);

    // load Q tile (64 rows x 64 halves, swizzled)
    {
        const __half* Qg = g_q + ((size_t)(b * LL + qbase)) * EE + h * DD;
        #pragma unroll
        for (int j = 0; j < 4; j++) {
            int idx = tid + j * 128;
            int row = idx >> 3, c = idx & 7;
            cp16(sQb + row * 128 + ((c ^ (row & 7)) << 4), Qg + (size_t)row * EE + c * 8);
        }
    }

    int kmax = g_cnt[b * LL + qbase + 63];
    int nt = (kmax + 63) >> 6;
    int r0g = qbase + wid * 16 + gid;
    int cq0 = g_cnt[b * LL + r0g];
    int cq1 = g_cnt[b * LL + r0g + 8];

    const __half* Kg = g_k + ((size_t)(b * LL)) * EE + h * DD;
    const __half* Vg = g_v + ((size_t)(b * LL)) * EE + h * DD;

    // preload tile 0
    if (nt > 0) {
        #pragma unroll
        for (int j = 0; j < 4; j++) {
            int idx = tid + j * 128;
            int row = idx >> 3, c = idx & 7;
            uint32_t off = row * 128 + ((c ^ (row & 7)) << 4);
            cp16(sKb0 + off, Kg + (size_t)row * EE + c * 8);
            cp16(sVb0 + off, Vg + (size_t)row * EE + c * 8);
        }
    }
    asm volatile("cp.async.commit_group;" ::: "memory");
    asm volatile("cp.async.wait_group 0;" ::: "memory");
    __syncthreads();

    // Q fragments (held in regs for whole kernel)
    uint32_t qf[4][4];
    #pragma unroll
    for (int ks = 0; ks < 4; ks++) {
        int r = wid * 16 + (lane & 15);
        int ch = ks * 2 + (lane >> 4);
        ldsm4(qf[ks], sQb + r * 128 + ((ch ^ (r & 7)) << 4));
    }

    float m0 = -1e30f, m1 = -1e30f, l0 = 0.f, l1 = 0.f;
    float oacc[8][4];
    #pragma unroll
    for (int ni = 0; ni < 8; ni++)
        #pragma unroll
        for (int r = 0; r < 4; r++) oacc[ni][r] = 0.f;

    for (int t = 0; t < nt; t++) {
        uint32_t Ks = (t & 1) ? sKb1 : sKb0;
        uint32_t Vs = (t & 1) ? sVb1 : sVb0;
        // prefetch next tile into other stage
        if (t + 1 < nt) {
            uint32_t Kn = (t & 1) ? sKb0 : sKb1;
            uint32_t Vn = (t & 1) ? sVb0 : sVb1;
            int koff = (t + 1) * 64;
            #pragma unroll
            for (int j = 0; j < 4; j++) {
                int idx = tid + j * 128;
                int row = idx >> 3, c = idx & 7;
                uint32_t off = row * 128 + ((c ^ (row & 7)) << 4);
                cp16(Kn + off, Kg + (size_t)(koff + row) * EE + c * 8);
                cp16(Vn + off, Vg + (size_t)(koff + row) * EE + c * 8);
            }
        }
        asm volatile("cp.async.commit_group;" ::: "memory");

        // S = Q @ K^T  (fp32 acc)
        float s[8][4];
        #pragma unroll
        for (int ni = 0; ni < 8; ni++)
            #pragma unroll
            for (int r = 0; r < 4; r++) s[ni][r] = 0.f;
        #pragma unroll
        for (int ks = 0; ks < 4; ks++) {
            #pragma unroll
            for (int ni = 0; ni < 8; ni++) {
                uint32_t kb[2];
                int r = ni * 8 + (lane & 7);
                int ch = ks * 2 + ((lane >> 3) & 1);
                ldsm2(kb, Ks + r * 128 + ((ch ^ (r & 7)) << 4));
                mma16816(s[ni], qf[ks], kb);
            }
        }

        // masked online softmax (finite sentinel; no NaNs)
        int k0 = t * 64;
        float rmax0 = -1e30f, rmax1 = -1e30f;
        #pragma unroll
        for (int ni = 0; ni < 8; ni++) {
            int cb = k0 + ni * 8 + tig * 2;
            s[ni][0] = (cb     < cq0) ? s[ni][0] * 0.125f : -1e30f;
            s[ni][1] = (cb + 1 < cq0) ? s[ni][1] * 0.125f : -1e30f;
            s[ni][2] = (cb     < cq1) ? s[ni][2] * 0.125f : -1e30f;
            s[ni][3] = (cb + 1 < cq1) ? s[ni][3] * 0.125f : -1e30f;
            rmax0 = fmaxf(rmax0, fmaxf(s[ni][0], s[ni][1]));
            rmax1 = fmaxf(rmax1, fmaxf(s[ni][2], s[ni][3]));
        }
        rmax0 = fmaxf(rmax0, __shfl_xor_sync(0xffffffffu, rmax0, 1));
        rmax0 = fmaxf(rmax0, __shfl_xor_sync(0xffffffffu, rmax0, 2));
        rmax1 = fmaxf(rmax1, __shfl_xor_sync(0xffffffffu, rmax1, 1));
        rmax1 = fmaxf(rmax1, __shfl_xor_sync(0xffffffffu, rmax1, 2));
        float mn0 = fmaxf(m0, rmax0), mn1 = fmaxf(m1, rmax1);
        float c0 = __expf(m0 - mn0), c1 = __expf(m1 - mn1);
        l0 *= c0; l1 *= c1;
        #pragma unroll
        for (int ni = 0; ni < 8; ni++) {
            oacc[ni][0] *= c0; oacc[ni][1] *= c0;
            oacc[ni][2] *= c1; oacc[ni][3] *= c1;
        }
        uint32_t p16[8][2];
        float ps0 = 0.f, ps1 = 0.f;
        #pragma unroll
        for (int ni = 0; ni < 8; ni++) {
            float p0 = __expf(s[ni][0] - mn0);
            float p1 = __expf(s[ni][1] - mn0);
            float p2 = __expf(s[ni][2] - mn1);
            float p3 = __expf(s[ni][3] - mn1);
            ps0 += p0 + p1; ps1 += p2 + p3;
            p16[ni][0] = h2u(__floats2half2_rn(p0, p1));
            p16[ni][1] = h2u(__floats2half2_rn(p2, p3));
        }
        l0 += ps0; l1 += ps1; m0 = mn0; m1 = mn1;

        // O += P @ V
        #pragma unroll
        for (int ks = 0; ks < 4; ks++) {
            uint32_t pa[4] = { p16[2*ks][0], p16[2*ks][1], p16[2*ks+1][0], p16[2*ks+1][1] };
            #pragma unroll
            for (int ni = 0; ni < 8; ni++) {
                uint32_t vb[2];
                int r = ks * 16 + (lane & 15);
                ldsm2t(vb, Vs + r * 128 + ((ni ^ (r & 7)) << 4));
                mma16816(oacc[ni], pa, vb);
            }
        }

        asm volatile("cp.async.wait_group 0;" ::: "memory");
        __syncthreads();
    }

    // reduce l across quad, write output
    l0 += __shfl_xor_sync(0xffffffffu, l0, 1);
    l0 += __shfl_xor_sync(0xffffffffu, l0, 2);
    l1 += __shfl_xor_sync(0xffffffffu, l1, 1);
    l1 += __shfl_xor_sync(0xffffffffu, l1, 2);
    float invl0 = (cq0 > 0 && l0 > 0.f) ? (1.0f / l0) : 0.f;
    float invl1 = (cq1 > 0 && l1 > 0.f) ? (1.0f / l1) : 0.f;

    __half* Y0 = g_y + ((size_t)(b * LL + r0g)) * EE + h * DD;
    __half* Y1 = g_y + ((size_t)(b * LL + r0g + 8)) * EE + h * DD;
    #pragma unroll
    for (int ni = 0; ni < 8; ni++) {
        int c = ni * 8 + tig * 2;
        *(__half2*)(Y0 + c) = __floats2half2_rn(oacc[ni][0] * invl0, oacc[ni][1] * invl0);
        *(__half2*)(Y1 + c) = __floats2half2_rn(oacc[ni][2] * invl1, oacc[ni][3] * invl1);
    }
}

// ---------------- launch ----------------
extern "C" void kernel_launch(void* const* d_in, const int* in_sizes, int n_in,
                              void* d_out, int out_size) {
    const float* x       = (const float*)d_in[0];
    const float* age     = (const float*)d_in[1];
    const int*   mod_idx = (const int*)  d_in[2];
    const float* mod_age = (const float*)d_in[3];
    const float* e2      = (const float*)d_in[4];
    const float* e3      = (const float*)d_in[5];
    const float* ln0w = (const float*)d_in[6];
    const float* ln0b = (const float*)d_in[7];
    const float* ln1w = (const float*)d_in[8];
    const float* ln1b = (const float*)d_in[9];
    const float* ln2w = (const float*)d_in[10];
    const float* ln2b = (const float*)d_in[11];
    const float* qw = (const float*)d_in[12];
    const float* qb = (const float*)d_in[13];
    const float* kw = (const float*)d_in[14];
    const float* kb = (const float*)d_in[15];
    const float* vw = (const float*)d_in[16];
    const float* vb = (const float*)d_in[17];
    const float* cw = (const float*)d_in[18];
    const float* cb = (const float*)d_in[19];
    const float* fcw = (const float*)d_in[20];
    const float* fcb = (const float*)d_in[21];
    const float* pw  = (const float*)d_in[22];
    const float* pb  = (const float*)d_in[23];
    float* out = (float*)d_out;

    __half *sn, *xn, *y, *xn2, *hbuf;
    __half *wc, *wfc, *wp;
    float *x1;
    cudaGetSymbolAddress((void**)&sn,  g_sn);
    cudaGetSymbolAddress((void**)&xn,  g_xn);
    cudaGetSymbolAddress((void**)&y,   g_y);
    cudaGetSymbolAddress((void**)&x1,  g_x1);
    cudaGetSymbolAddress((void**)&xn2, g_xn2);
    cudaGetSymbolAddress((void**)&hbuf, g_h);
    cudaGetSymbolAddress((void**)&wc,  g_wc);
    cudaGetSymbolAddress((void**)&wfc, g_wfc);
    cudaGetSymbolAddress((void**)&wp,  g_wp);

    cudaFuncSetAttribute((const void*)tc_gemm<1, float>,  cudaFuncAttributeMaxDynamicSharedMemorySize, GEMM_SMEM);
    cudaFuncSetAttribute((const void*)tc_gemm<2, __half>, cudaFuncAttributeMaxDynamicSharedMemorySize, GEMM_SMEM);
    cudaFuncSetAttribute((const void*)qkv_gemm,           cudaFuncAttributeMaxDynamicSharedMemorySize, GEMM_SMEM);

    // 0. convert all weights to fp16 in one launch
    {
        const int total = 4*(EE*EE/4) + 2*(FF*EE/4);
        round_w_all<<<(total + 255)/256, 256>>>(qw, kw, vw, cw, fcw, pw);
    }

    // 1. fuse-embed occurrence indices + mask prefix lengths
    fuse_idx_kernel<<<BB, 1024>>>(mod_idx);
    cnt_kernel<<<BB, 1024>>>(age, mod_age);

    // 2. LN0(gathered mod embeddings) -> sn ; LN1(x) -> xn   (fp16 out)
    gather_ln_kernel<<<MTOT, 256>>>(mod_idx, e2, e3, ln0w, ln0b, sn);
    ln_kernel<<<MTOT, 256>>>(x, ln1w, ln1b, xn);

    // 3. fused QKV projection (fp16 mma)
    qkv_gemm<<<dim3(18, 32), GTHREADS, GEMM_SMEM>>>(qb, kb, vb);

    // 4. tensor-core prefix-masked flash attention -> y (fp16)
    attn_kernel<<<dim3(LL / 64, BB * HH), 128>>>();

    // 5. out projection + residual -> x1 (fp32)
    tc_gemm<1, float><<<dim3(6, 32), GTHREADS, GEMM_SMEM>>>(y, wc, cb, x, x1, EE, EE);

    // 6. LN2 -> xn2 ; MLP with GELU ; proj + residual -> out
    ln_kernel<<<MTOT, 256>>>(x1, ln2w, ln2b, xn2);
    tc_gemm<2, __half><<<dim3(24, 32), GTHREADS, GEMM_SMEM>>>(xn2, wfc, fcb, nullptr, hbuf, EE, FF);
    tc_gemm<1, float><<<dim3(6, 32), GTHREADS, GEMM_SMEM>>>(hbuf, wp, pb, x1, out, FF, EE);
}

// round 12
// speedup vs baseline: 5.2561x; 1.5627x over previous
#include <cuda_runtime.h>
#include <cuda_fp16.h>
#include <math.h>
#include <stdint.h>

#define BB 4
#define LL 1024
#define EE 768
#define HH 12
#define DD 64
#define HALF 512
#define FF 3072
#define MTOT (BB*LL)   // 4096

// ---------------- scratch (no allocations allowed) ----------------
__device__ __half g_sn [MTOT*EE];
__device__ __half g_xn [MTOT*EE];
__device__ __half g_q  [MTOT*EE];
__device__ __half g_k  [MTOT*EE];
__device__ __half g_v  [MTOT*EE];
__device__ __half g_y  [MTOT*EE];
__device__ float  g_x1 [MTOT*EE];
__device__ __half g_xn2[MTOT*EE];
__device__ __half g_h  [MTOT*FF];
__device__ int    g_gidx[MTOT];
__device__ int    g_cnt [MTOT];
// fp16 weights
__device__ __half g_wq [EE*EE];
__device__ __half g_wk [EE*EE];
__device__ __half g_wv [EE*EE];
__device__ __half g_wc [EE*EE];
__device__ __half g_wfc[FF*EE];
__device__ __half g_wp [EE*FF];

__device__ __forceinline__ uint32_t h2u(__half2 h) {
    return *reinterpret_cast<uint32_t*>(&h);
}

// ---------------- fused weight conversion fp32 -> fp16 ----------------
__global__ void round_w_all(const float* __restrict__ qw, const float* __restrict__ kw,
                            const float* __restrict__ vw, const float* __restrict__ cw,
                            const float* __restrict__ fcw, const float* __restrict__ pw) {
    const int S  = EE*EE/4;
    const int SF = FF*EE/4;
    int i = blockIdx.x * blockDim.x + threadIdx.x;
    const float* src; __half* dst; int off;
    if      (i <     S)      { src = qw;  dst = g_wq;  off = i; }
    else if (i < 2*S)        { src = kw;  dst = g_wk;  off = i - S; }
    else if (i < 3*S)        { src = vw;  dst = g_wv;  off = i - 2*S; }
    else if (i < 4*S)        { src = cw;  dst = g_wc;  off = i - 3*S; }
    else if (i < 4*S + SF)   { src = fcw; dst = g_wfc; off = i - 4*S; }
    else if (i < 4*S + 2*SF) { src = pw;  dst = g_wp;  off = i - 4*S - SF; }
    else return;
    float4 v = ((const float4*)src)[off];
    __half2* d = (__half2*)(dst + (size_t)off * 4);
    d[0] = __floats2half2_rn(v.x, v.y);
    d[1] = __floats2half2_rn(v.z, v.w);
}

// ---------------- fuse-embed index scan ----------------
__global__ void fuse_idx_kernel(const int* __restrict__ mod_idx) {
    __shared__ int sbuf[1024];
    int b = blockIdx.x, j = threadIdx.x;
    int v = mod_idx[b*LL + j];
    int is2 = (v == 2) ? 1 : 0;
    sbuf[j] = is2;
    __syncthreads();
    #pragma unroll
    for (int off = 1; off < 1024; off <<= 1) {
        int t = (j >= off) ? sbuf[j - off] : 0;
        __syncthreads();
        sbuf[j] += t;
        __syncthreads();
    }
    int p2  = sbuf[j];
    int occ = is2 ? (p2 - 1) : (j - p2);
    occ = min(max(occ, 0), HALF - 1);
    g_gidx[b*LL + j] = b*HALF + occ;
}

// ---------------- prefix-length (mask) kernel ----------------
__global__ void cnt_kernel(const float* __restrict__ age,
                           const float* __restrict__ mod_age) {
    int b = blockIdx.x, q = threadIdx.x;
    float a = age[b*LL + q];
    const float* ma = mod_age + b*LL;
    int lo = 0, hi = LL;
    while (lo < hi) {
        int mid = (lo + hi) >> 1;
        if (ma[mid] <= a) lo = mid + 1; else hi = mid;
    }
    g_cnt[b*LL + q] = lo;
}

// ---------------- LayerNorm: one warp per row, shfl-only ----------------
__device__ __forceinline__ void ln_row_warp(const float* __restrict__ p,
                                            const float* __restrict__ w,
                                            const float* __restrict__ bia,
                                            __half* __restrict__ d, int lane) {
    float v[24];
    float s = 0.f, ss = 0.f;
    #pragma unroll
    for (int k = 0; k < 24; k++) {
        v[k] = p[lane + k * 32];
        s += v[k];
        ss = fmaf(v[k], v[k], ss);
    }
    #pragma unroll
    for (int o = 16; o; o >>= 1) {
        s  += __shfl_xor_sync(0xffffffffu, s,  o);
        ss += __shfl_xor_sync(0xffffffffu, ss, o);
    }
    float mean = s * (1.0f / 768.0f);
    float var  = ss * (1.0f / 768.0f) - mean * mean;
    float inv  = rsqrtf(var + 1e-5f);
    #pragma unroll
    for (int k = 0; k < 24; k++) {
        int j = lane + k * 32;
        d[j] = __float2half_rn((v[k] - mean) * inv * w[j] + bia[j]);
    }
}

__global__ void ln_kernel(const float* __restrict__ src,
                          const float* __restrict__ w,
                          const float* __restrict__ bia,
                          __half* __restrict__ dst) {
    int warp = threadIdx.x >> 5, lane = threadIdx.x & 31;
    int row = blockIdx.x * 8 + warp;
    ln_row_warp(src + (size_t)row * EE, w, bia, dst + (size_t)row * EE, lane);
}

__global__ void gather_ln_kernel(const int* __restrict__ mod_idx,
                                 const float* __restrict__ e2,
                                 const float* __restrict__ e3,
                                 const float* __restrict__ w,
                                 const float* __restrict__ bia,
                                 __half* __restrict__ dst) {
    int warp = threadIdx.x >> 5, lane = threadIdx.x & 31;
    int row = blockIdx.x * 8 + warp;
    int sel = mod_idx[row];
    const float* src = ((sel == 2) ? e2 : e3) + (size_t)g_gidx[row] * EE;
    ln_row_warp(src, w, bia, dst + (size_t)row * EE, lane);
}

// =====================================================================
// shared mma helpers
// =====================================================================
__device__ __forceinline__ float gelu_exact(float x) {
    return 0.5f * x * (1.0f + erff(x * 0.70710678118654752440f));
}

__device__ __forceinline__ void cp16(uint32_t dst, const void* src) {
    asm volatile("cp.async.cg.shared.global [%0], [%1], 16;" :: "r"(dst), "l"(src));
}
__device__ __forceinline__ void ldsm4(uint32_t* r, uint32_t addr) {
    asm volatile("ldmatrix.sync.aligned.m8n8.x4.shared.b16 {%0,%1,%2,%3}, [%4];"
                 : "=r"(r[0]), "=r"(r[1]), "=r"(r[2]), "=r"(r[3]) : "r"(addr));
}
__device__ __forceinline__ void ldsm2(uint32_t* r, uint32_t addr) {
    asm volatile("ldmatrix.sync.aligned.m8n8.x2.shared.b16 {%0,%1}, [%2];"
                 : "=r"(r[0]), "=r"(r[1]) : "r"(addr));
}
__device__ __forceinline__ void ldsm2t(uint32_t* r, uint32_t addr) {
    asm volatile("ldmatrix.sync.aligned.m8n8.x2.trans.shared.b16 {%0,%1}, [%2];"
                 : "=r"(r[0]), "=r"(r[1]) : "r"(addr));
}
__device__ __forceinline__ void mma16816(float* c, const uint32_t* a, const uint32_t* b) {
    asm volatile(
        "mma.sync.aligned.m16n8k16.row.col.f32.f16.f16.f32 "
        "{%0,%1,%2,%3}, {%4,%5,%6,%7}, {%8,%9}, {%0,%1,%2,%3};"
        : "+f"(c[0]), "+f"(c[1]), "+f"(c[2]), "+f"(c[3])
        : "r"(a[0]), "r"(a[1]), "r"(a[2]), "r"(a[3]), "r"(b[0]), "r"(b[1]));
}

// =====================================================================
// fp16 mma GEMM: C[M,N] = A[M,K] @ W[N,K]^T (+bias, +res/GELU)
// CTA 128x128, 8 warps (64x32 tiles), K-chunk 64, 3-stage cp.async,
// single __syncthreads per iter, 2 CTAs/SM.
// =====================================================================
#define NSTAGE 3
#define STG_BYTES (2*128*128)            // 32 KB per stage
#define GEMM_SMEM (NSTAGE*STG_BYTES)     // 98304
#define GTHREADS 256

__device__ __forceinline__ void load_tile(const __half* __restrict__ A,
                                          const __half* __restrict__ W,
                                          int K, int tM, int tN, int k0,
                                          uint32_t sA, int tid) {
    uint32_t sB = sA + 128 * 128;
    #pragma unroll
    for (int j = 0; j < 4; j++) {
        int idx = tid + j * GTHREADS;
        int row = idx >> 3, c = idx & 7;
        uint32_t off = (uint32_t)(row * 128 + ((c ^ (row & 7)) << 4));
        cp16(sA + off, A + (size_t)(tM + row) * K + k0 + c * 8);
        cp16(sB + off, W + (size_t)(tN + row) * K + k0 + c * 8);
    }
}

template <int EPI, typename OT>
__device__ __forceinline__ void gemm_body(const __half* __restrict__ A,
                                          const __half* __restrict__ W,
                                          const float* __restrict__ bias,
                                          const float* __restrict__ R,
                                          OT* __restrict__ C,
                                          int K, int N, int tM, int tN) {
    extern __shared__ __align__(16) char smem[];
    uint32_t smem_b = (uint32_t)__cvta_generic_to_shared(smem);
    int tid = threadIdx.x, wid = tid >> 5, lane = tid & 31;
    int wm = wid & 1, wn = wid >> 1;
    int gid = lane >> 2, tig = lane & 3;

    const int iters = K >> 6;

    float acc[4][4][4];
    #pragma unroll
    for (int mi = 0; mi < 4; mi++)
        #pragma unroll
        for (int ni = 0; ni < 4; ni++)
            #pragma unroll
            for (int r = 0; r < 4; r++) acc[mi][ni][r] = 0.f;

    // prologue: issue loads for stages 0..NSTAGE-2
    #pragma unroll
    for (int s = 0; s < NSTAGE - 1; s++) {
        if (s < iters)
            load_tile(A, W, K, tM, tN, s * 64, smem_b + s * STG_BYTES, tid);
        asm volatile("cp.async.commit_group;" ::: "memory");
    }

    int a_row = wm * 64 + (lane & 15);
    int a_kc  = lane >> 4;
    int b_row = wn * 32 + (lane & 7);
    int b_kc  = (lane >> 3) & 1;

    int stage = 0;
    for (int i = 0; i < iters; i++) {
        asm volatile("cp.async.wait_group %0;" :: "n"(NSTAGE - 2) : "memory");
        __syncthreads();

        // issue load for i+NSTAGE-1 into stage (i+NSTAGE-1)%NSTAGE
        // (that stage was last read at iter i-1; the barrier above covers WAR)
        int li = i + NSTAGE - 1;
        if (li < iters) {
            int lst = li % NSTAGE;
            load_tile(A, W, K, tM, tN, li * 64, smem_b + lst * STG_BYTES, tid);
        }
        asm volatile("cp.async.commit_group;" ::: "memory");

        uint32_t As = smem_b + stage * STG_BYTES;
        uint32_t Bs = As + 128 * 128;

        #pragma unroll
        for (int ks = 0; ks < 4; ks++) {
            uint32_t a[4][4], b[4][2];
            #pragma unroll
            for (int mi = 0; mi < 4; mi++) {
                int r = a_row + mi * 16;
                int kc = ks * 2 + a_kc;
                ldsm4(a[mi], As + r * 128 + ((kc ^ (r & 7)) << 4));
            }
            #pragma unroll
            for (int ni = 0; ni < 4; ni++) {
                int r = b_row + ni * 8;
                int kc = ks * 2 + b_kc;
                ldsm2(b[ni], Bs + r * 128 + ((kc ^ (r & 7)) << 4));
            }
            #pragma unroll
            for (int mi = 0; mi < 4; mi++)
                #pragma unroll
                for (int ni = 0; ni < 4; ni++)
                    mma16816(acc[mi][ni], a[mi], b[ni]);
        }
        stage = (stage + 1 == NSTAGE) ? 0 : stage + 1;
    }

    #pragma unroll
    for (int mi = 0; mi < 4; mi++) {
        int r0 = tM + wm * 64 + mi * 16 + gid;
        #pragma unroll
        for (int ni = 0; ni < 4; ni++) {
            int c = tN + wn * 32 + ni * 8 + tig * 2;
            float bx = bias[c], by = bias[c + 1];
            float2 v0 = make_float2(acc[mi][ni][0] + bx, acc[mi][ni][1] + by);
            float2 v1 = make_float2(acc[mi][ni][2] + bx, acc[mi][ni][3] + by);
            size_t o0 = (size_t)r0 * N + c;
            size_t o1 = (size_t)(r0 + 8) * N + c;
            if (EPI == 1) {
                float2 rr0 = *(const float2*)(R + o0);
                float2 rr1 = *(const float2*)(R + o1);
                v0.x += rr0.x; v0.y += rr0.y;
                v1.x += rr1.x; v1.y += rr1.y;
                *(float2*)((float*)C + o0) = v0;
                *(float2*)((float*)C + o1) = v1;
            } else {
                if (EPI == 2) {
                    v0.x = gelu_exact(v0.x); v0.y = gelu_exact(v0.y);
                    v1.x = gelu_exact(v1.x); v1.y = gelu_exact(v1.y);
                }
                *(__half2*)((__half*)C + o0) = __floats2half2_rn(v0.x, v0.y);
                *(__half2*)((__half*)C + o1) = __floats2half2_rn(v1.x, v1.y);
            }
        }
    }
}

template <int EPI, typename OT>
__global__ __launch_bounds__(GTHREADS, 2)
void tc_gemm(const __half* __restrict__ A, const __half* __restrict__ W,
             const float* __restrict__ bias, const float* __restrict__ R,
             OT* __restrict__ C, int K, int N) {
    gemm_body<EPI, OT>(A, W, bias, R, C, K, N, blockIdx.y * 128, blockIdx.x * 128);
}

__global__ __launch_bounds__(GTHREADS, 2)
void qkv_gemm(const float* __restrict__ qb, const float* __restrict__ kb,
              const float* __restrict__ vb) {
    int part = blockIdx.x / 6;
    int bx   = blockIdx.x % 6;
    const __half* A    = (part == 0) ? g_xn : g_sn;
    const __half* W    = (part == 0) ? g_wq : (part == 1) ? g_wk : g_wv;
    const float* bias  = (part == 0) ? qb   : (part == 1) ? kb   : vb;
    __half* C          = (part == 0) ? g_q  : (part == 1) ? g_k  : g_v;
    gemm_body<0, __half>(A, W, bias, nullptr, C, EE, EE, blockIdx.y * 128, bx * 128);
}

// =====================================================================
// tensor-core prefix-masked flash attention
// CTA: 64 queries, 4 warps (16 q-rows each), K-tiles of 64, double buffer.
// =====================================================================
__global__ __launch_bounds__(128)
void attn_kernel() {
    __shared__ __align__(16) __half sQ[64 * 64];
    __shared__ __align__(16) __half sK[2][64 * 64];
    __shared__ __align__(16) __half sV[2][64 * 64];

    int bh = blockIdx.y, b = bh / HH, h = bh - b * HH;
    int qbase = blockIdx.x * 64;
    int tid = threadIdx.x, wid = tid >> 5, lane = tid & 31;
    int gid = lane >> 2, tig = lane & 3;

    uint32_t sQb = (uint32_t)__cvta_generic_to_shared(sQ);
    uint32_t sKb0 = (uint32_t)__cvta_generic_to_shared(sK[0]);
    uint32_t sKb1 = (uint32_t)__cvta_generic_to_shared(sK[1]);
    uint32_t sVb0 = (uint32_t)__cvta_generic_to_shared(sV[0]);
    uint32_t sVb1 = (uint32_t)__cvta_generic_to_shared(sV[1]);

    // load Q tile (64 rows x 64 halves, swizzled)
    {
        const __half* Qg = g_q + ((size_t)(b * LL + qbase)) * EE + h * DD;
        #pragma unroll
        for (int j = 0; j < 4; j++) {
            int idx = tid + j * 128;
            int row = idx >> 3, c = idx & 7;
            cp16(sQb + row * 128 + ((c ^ (row & 7)) << 4), Qg + (size_t)row * EE + c * 8);
        }
    }

    int kmax = g_cnt[b * LL + qbase + 63];
    int nt = (kmax + 63) >> 6;
    int r0g = qbase + wid * 16 + gid;
    int cq0 = g_cnt[b * LL + r0g];
    int cq1 = g_cnt[b * LL + r0g + 8];

    const __half* Kg = g_k + ((size_t)(b * LL)) * EE + h * DD;
    const __half* Vg = g_v + ((size_t)(b * LL)) * EE + h * DD;

    // preload tile 0
    if (nt > 0) {
        #pragma unroll
        for (int j = 0; j < 4; j++) {
            int idx = tid + j * 128;
            int row = idx >> 3, c = idx & 7;
            uint32_t off = row * 128 + ((c ^ (row & 7)) << 4);
            cp16(sKb0 + off, Kg + (size_t)row * EE + c * 8);
            cp16(sVb0 + off, Vg + (size_t)row * EE + c * 8);
        }
    }
    asm volatile("cp.async.commit_group;" ::: "memory");
    asm volatile("cp.async.wait_group 0;" ::: "memory");
    __syncthreads();

    // Q fragments (held in regs for whole kernel)
    uint32_t qf[4][4];
    #pragma unroll
    for (int ks = 0; ks < 4; ks++) {
        int r = wid * 16 + (lane & 15);
        int ch = ks * 2 + (lane >> 4);
        ldsm4(qf[ks], sQb + r * 128 + ((ch ^ (r & 7)) << 4));
    }

    float m0 = -1e30f, m1 = -1e30f, l0 = 0.f, l1 = 0.f;
    float oacc[8][4];
    #pragma unroll
    for (int ni = 0; ni < 8; ni++)
        #pragma unroll
        for (int r = 0; r < 4; r++) oacc[ni][r] = 0.f;

    for (int t = 0; t < nt; t++) {
        uint32_t Ks = (t & 1) ? sKb1 : sKb0;
        uint32_t Vs = (t & 1) ? sVb1 : sVb0;
        // prefetch next tile into other stage
        if (t + 1 < nt) {
            uint32_t Kn = (t & 1) ? sKb0 : sKb1;
            uint32_t Vn = (t & 1) ? sVb0 : sVb1;
            int koff = (t + 1) * 64;
            #pragma unroll
            for (int j = 0; j < 4; j++) {
                int idx = tid + j * 128;
                int row = idx >> 3, c = idx & 7;
                uint32_t off = row * 128 + ((c ^ (row & 7)) << 4);
                cp16(Kn + off, Kg + (size_t)(koff + row) * EE + c * 8);
                cp16(Vn + off, Vg + (size_t)(koff + row) * EE + c * 8);
            }
        }
        asm volatile("cp.async.commit_group;" ::: "memory");

        // S = Q @ K^T  (fp32 acc)
        float s[8][4];
        #pragma unroll
        for (int ni = 0; ni < 8; ni++)
            #pragma unroll
            for (int r = 0; r < 4; r++) s[ni][r] = 0.f;
        #pragma unroll
        for (int ks = 0; ks < 4; ks++) {
            #pragma unroll
            for (int ni = 0; ni < 8; ni++) {
                uint32_t kb[2];
                int r = ni * 8 + (lane & 7);
                int ch = ks * 2 + ((lane >> 3) & 1);
                ldsm2(kb, Ks + r * 128 + ((ch ^ (r & 7)) << 4));
                mma16816(s[ni], qf[ks], kb);
            }
        }

        // masked online softmax (finite sentinel; no NaNs)
        int k0 = t * 64;
        float rmax0 = -1e30f, rmax1 = -1e30f;
        #pragma unroll
        for (int ni = 0; ni < 8; ni++) {
            int cb = k0 + ni * 8 + tig * 2;
            s[ni][0] = (cb     < cq0) ? s[ni][0] * 0.125f : -1e30f;
            s[ni][1] = (cb + 1 < cq0) ? s[ni][1] * 0.125f : -1e30f;
            s[ni][2] = (cb     < cq1) ? s[ni][2] * 0.125f : -1e30f;
            s[ni][3] = (cb + 1 < cq1) ? s[ni][3] * 0.125f : -1e30f;
            rmax0 = fmaxf(rmax0, fmaxf(s[ni][0], s[ni][1]));
            rmax1 = fmaxf(rmax1, fmaxf(s[ni][2], s[ni][3]));
        }
        rmax0 = fmaxf(rmax0, __shfl_xor_sync(0xffffffffu, rmax0, 1));
        rmax0 = fmaxf(rmax0, __shfl_xor_sync(0xffffffffu, rmax0, 2));
        rmax1 = fmaxf(rmax1, __shfl_xor_sync(0xffffffffu, rmax1, 1));
        rmax1 = fmaxf(rmax1, __shfl_xor_sync(0xffffffffu, rmax1, 2));
        float mn0 = fmaxf(m0, rmax0), mn1 = fmaxf(m1, rmax1);
        float c0 = __expf(m0 - mn0), c1 = __expf(m1 - mn1);
        l0 *= c0; l1 *= c1;
        #pragma unroll
        for (int ni = 0; ni < 8; ni++) {
            oacc[ni][0] *= c0; oacc[ni][1] *= c0;
            oacc[ni][2] *= c1; oacc[ni][3] *= c1;
        }
        uint32_t p16[8][2];
        float ps0 = 0.f, ps1 = 0.f;
        #pragma unroll
        for (int ni = 0; ni < 8; ni++) {
            float p0 = __expf(s[ni][0] - mn0);
            float p1 = __expf(s[ni][1] - mn0);
            float p2 = __expf(s[ni][2] - mn1);
            float p3 = __expf(s[ni][3] - mn1);
            ps0 += p0 + p1; ps1 += p2 + p3;
            p16[ni][0] = h2u(__floats2half2_rn(p0, p1));
            p16[ni][1] = h2u(__floats2half2_rn(p2, p3));
        }
        l0 += ps0; l1 += ps1; m0 = mn0; m1 = mn1;

        // O += P @ V
        #pragma unroll
        for (int ks = 0; ks < 4; ks++) {
            uint32_t pa[4] = { p16[2*ks][0], p16[2*ks][1], p16[2*ks+1][0], p16[2*ks+1][1] };
            #pragma unroll
            for (int ni = 0; ni < 8; ni++) {
                uint32_t vb[2];
                int r = ks * 16 + (lane & 15);
                ldsm2t(vb, Vs + r * 128 + ((ni ^ (r & 7)) << 4));
                mma16816(oacc[ni], pa, vb);
            }
        }

        asm volatile("cp.async.wait_group 0;" ::: "memory");
        __syncthreads();
    }

    // reduce l across quad, write output
    l0 += __shfl_xor_sync(0xffffffffu, l0, 1);
    l0 += __shfl_xor_sync(0xffffffffu, l0, 2);
    l1 += __shfl_xor_sync(0xffffffffu, l1, 1);
    l1 += __shfl_xor_sync(0xffffffffu, l1, 2);
    float invl0 = (cq0 > 0 && l0 > 0.f) ? (1.0f / l0) : 0.f;
    float invl1 = (cq1 > 0 && l1 > 0.f) ? (1.0f / l1) : 0.f;

    __half* Y0 = g_y + ((size_t)(b * LL + r0g)) * EE + h * DD;
    __half* Y1 = g_y + ((size_t)(b * LL + r0g + 8)) * EE + h * DD;
    #pragma unroll
    for (int ni = 0; ni < 8; ni++) {
        int c = ni * 8 + tig * 2;
        *(__half2*)(Y0 + c) = __floats2half2_rn(oacc[ni][0] * invl0, oacc[ni][1] * invl0);
        *(__half2*)(Y1 + c) = __floats2half2_rn(oacc[ni][2] * invl1, oacc[ni][3] * invl1);
    }
}

// ---------------- launch ----------------
extern "C" void kernel_launch(void* const* d_in, const int* in_sizes, int n_in,
                              void* d_out, int out_size) {
    const float* x       = (const float*)d_in[0];
    const float* age     = (const float*)d_in[1];
    const int*   mod_idx = (const int*)  d_in[2];
    const float* mod_age = (const float*)d_in[3];
    const float* e2      = (const float*)d_in[4];
    const float* e3      = (const float*)d_in[5];
    const float* ln0w = (const float*)d_in[6];
    const float* ln0b = (const float*)d_in[7];
    const float* ln1w = (const float*)d_in[8];
    const float* ln1b = (const float*)d_in[9];
    const float* ln2w = (const float*)d_in[10];
    const float* ln2b = (const float*)d_in[11];
    const float* qw = (const float*)d_in[12];
    const float* qb = (const float*)d_in[13];
    const float* kw = (const float*)d_in[14];
    const float* kb = (const float*)d_in[15];
    const float* vw = (const float*)d_in[16];
    const float* vb = (const float*)d_in[17];
    const float* cw = (const float*)d_in[18];
    const float* cb = (const float*)d_in[19];
    const float* fcw = (const float*)d_in[20];
    const float* fcb = (const float*)d_in[21];
    const float* pw  = (const float*)d_in[22];
    const float* pb  = (const float*)d_in[23];
    float* out = (float*)d_out;

    __half *sn, *xn, *y, *xn2, *hbuf;
    __half *wc, *wfc, *wp;
    float *x1;
    cudaGetSymbolAddress((void**)&sn,  g_sn);
    cudaGetSymbolAddress((void**)&xn,  g_xn);
    cudaGetSymbolAddress((void**)&y,   g_y);
    cudaGetSymbolAddress((void**)&x1,  g_x1);
    cudaGetSymbolAddress((void**)&xn2, g_xn2);
    cudaGetSymbolAddress((void**)&hbuf, g_h);
    cudaGetSymbolAddress((void**)&wc,  g_wc);
    cudaGetSymbolAddress((void**)&wfc, g_wfc);
    cudaGetSymbolAddress((void**)&wp,  g_wp);

    cudaFuncSetAttribute((const void*)tc_gemm<1, float>,  cudaFuncAttributeMaxDynamicSharedMemorySize, GEMM_SMEM);
    cudaFuncSetAttribute((const void*)tc_gemm<2, __half>, cudaFuncAttributeMaxDynamicSharedMemorySize, GEMM_SMEM);
    cudaFuncSetAttribute((const void*)qkv_gemm,           cudaFuncAttributeMaxDynamicSharedMemorySize, GEMM_SMEM);

    // 0. convert all weights to fp16 in one launch
    {
        const int total = 4*(EE*EE/4) + 2*(FF*EE/4);
        round_w_all<<<(total + 255)/256, 256>>>(qw, kw, vw, cw, fcw, pw);
    }

    // 1. fuse-embed occurrence indices + mask prefix lengths
    fuse_idx_kernel<<<BB, 1024>>>(mod_idx);
    cnt_kernel<<<BB, 1024>>>(age, mod_age);

    // 2. LN0(gathered mod embeddings) -> sn ; LN1(x) -> xn  (warp-per-row)
    gather_ln_kernel<<<MTOT/8, 256>>>(mod_idx, e2, e3, ln0w, ln0b, sn);
    ln_kernel<<<MTOT/8, 256>>>(x, ln1w, ln1b, xn);

    // 3. fused QKV projection (fp16 mma)
    qkv_gemm<<<dim3(18, 32), GTHREADS, GEMM_SMEM>>>(qb, kb, vb);

    // 4. tensor-core prefix-masked flash attention -> y (fp16)
    attn_kernel<<<dim3(LL / 64, BB * HH), 128>>>();

    // 5. out projection + residual -> x1 (fp32)
    tc_gemm<1, float><<<dim3(6, 32), GTHREADS, GEMM_SMEM>>>(y, wc, cb, x, x1, EE, EE);

    // 6. LN2 -> xn2 ; MLP with GELU ; proj + residual -> out
    ln_kernel<<<MTOT/8, 256>>>(x1, ln2w, ln2b, xn2);
    tc_gemm<2, __half><<<dim3(24, 32), GTHREADS, GEMM_SMEM>>>(xn2, wfc, fcb, nullptr, hbuf, EE, FF);
    tc_gemm<1, float><<<dim3(6, 32), GTHREADS, GEMM_SMEM>>>(hbuf, wp, pb, x1, out, FF, EE);
}

// round 13
// speedup vs baseline: 5.9182x; 1.1260x over previous
#include <cuda_runtime.h>
#include <cuda_fp16.h>
#include <math.h>
#include <stdint.h>

#define BB 4
#define LL 1024
#define EE 768
#define HH 12
#define DD 64
#define HALF 512
#define FF 3072
#define MTOT (BB*LL)   // 4096

// ---------------- scratch (no allocations allowed) ----------------
__device__ __half g_sn [MTOT*EE];
__device__ __half g_xn [MTOT*EE];
__device__ __half g_q  [MTOT*EE];
__device__ __half g_k  [MTOT*EE];
__device__ __half g_v  [MTOT*EE];
__device__ __half g_y  [MTOT*EE];
__device__ float  g_x1 [MTOT*EE];
__device__ __half g_xn2[MTOT*EE];
__device__ __half g_h  [MTOT*FF];
__device__ int    g_gidx[MTOT];
__device__ int    g_cnt [MTOT];
// fp16 weights
__device__ __half g_wq [EE*EE];
__device__ __half g_wk [EE*EE];
__device__ __half g_wv [EE*EE];
__device__ __half g_wc [EE*EE];
__device__ __half g_wfc[FF*EE];
__device__ __half g_wp [EE*FF];

__device__ __forceinline__ uint32_t h2u(__half2 h) {
    return *reinterpret_cast<uint32_t*>(&h);
}

// ---------------- fused weight conversion fp32 -> fp16 ----------------
__global__ void round_w_all(const float* __restrict__ qw, const float* __restrict__ kw,
                            const float* __restrict__ vw, const float* __restrict__ cw,
                            const float* __restrict__ fcw, const float* __restrict__ pw) {
    const int S  = EE*EE/4;
    const int SF = FF*EE/4;
    int i = blockIdx.x * blockDim.x + threadIdx.x;
    const float* src; __half* dst; int off;
    if      (i <     S)      { src = qw;  dst = g_wq;  off = i; }
    else if (i < 2*S)        { src = kw;  dst = g_wk;  off = i - S; }
    else if (i < 3*S)        { src = vw;  dst = g_wv;  off = i - 2*S; }
    else if (i < 4*S)        { src = cw;  dst = g_wc;  off = i - 3*S; }
    else if (i < 4*S + SF)   { src = fcw; dst = g_wfc; off = i - 4*S; }
    else if (i < 4*S + 2*SF) { src = pw;  dst = g_wp;  off = i - 4*S - SF; }
    else return;
    float4 v = ((const float4*)src)[off];
    __half2* d = (__half2*)(dst + (size_t)off * 4);
    d[0] = __floats2half2_rn(v.x, v.y);
    d[1] = __floats2half2_rn(v.z, v.w);
}

// ---------------- fused prep: fuse-embed scan + prefix lengths ----------
__global__ void prep_kernel(const int* __restrict__ mod_idx,
                            const float* __restrict__ age,
                            const float* __restrict__ mod_age) {
    int j = threadIdx.x;
    if (blockIdx.x < BB) {
        __shared__ int sbuf[1024];
        int b = blockIdx.x;
        int v = mod_idx[b*LL + j];
        int is2 = (v == 2) ? 1 : 0;
        sbuf[j] = is2;
        __syncthreads();
        #pragma unroll
        for (int off = 1; off < 1024; off <<= 1) {
            int t = (j >= off) ? sbuf[j - off] : 0;
            __syncthreads();
            sbuf[j] += t;
            __syncthreads();
        }
        int p2  = sbuf[j];
        int occ = is2 ? (p2 - 1) : (j - p2);
        occ = min(max(occ, 0), HALF - 1);
        g_gidx[b*LL + j] = b*HALF + occ;
    } else {
        int b = blockIdx.x - BB;
        float a = age[b*LL + j];
        const float* ma = mod_age + b*LL;
        int lo = 0, hi = LL;
        while (lo < hi) {
            int mid = (lo + hi) >> 1;
            if (ma[mid] <= a) lo = mid + 1; else hi = mid;
        }
        g_cnt[b*LL + j] = lo;
    }
}

// ---------------- LayerNorm: one warp per row, float4, shfl-only --------
__device__ __forceinline__ void ln_row_warp(const float* __restrict__ p,
                                            const float* __restrict__ w,
                                            const float* __restrict__ bia,
                                            __half* __restrict__ d, int lane) {
    float4 v[6];
    float s = 0.f, ss = 0.f;
    #pragma unroll
    for (int k = 0; k < 6; k++) {
        v[k] = ((const float4*)p)[lane + k * 32];
        s += (v[k].x + v[k].y) + (v[k].z + v[k].w);
        ss = fmaf(v[k].x, v[k].x, fmaf(v[k].y, v[k].y,
             fmaf(v[k].z, v[k].z, fmaf(v[k].w, v[k].w, ss))));
    }
    #pragma unroll
    for (int o = 16; o; o >>= 1) {
        s  += __shfl_xor_sync(0xffffffffu, s,  o);
        ss += __shfl_xor_sync(0xffffffffu, ss, o);
    }
    float mean = s * (1.0f / 768.0f);
    float var  = ss * (1.0f / 768.0f) - mean * mean;
    float inv  = rsqrtf(var + 1e-5f);
    #pragma unroll
    for (int k = 0; k < 6; k++) {
        int f4 = lane + k * 32;
        float4 ww = ((const float4*)w)[f4];
        float4 bb = ((const float4*)bia)[f4];
        __half2 h0 = __floats2half2_rn((v[k].x - mean) * inv * ww.x + bb.x,
                                       (v[k].y - mean) * inv * ww.y + bb.y);
        __half2 h1 = __floats2half2_rn((v[k].z - mean) * inv * ww.z + bb.z,
                                       (v[k].w - mean) * inv * ww.w + bb.w);
        *(__half2*)(d + f4 * 4)     = h0;
        *(__half2*)(d + f4 * 4 + 2) = h1;
    }
}

// merged LN0(gather) + LN1(x): blockIdx.x < 512 -> sn, else -> xn
__global__ void ln01_kernel(const int* __restrict__ mod_idx,
                            const float* __restrict__ e2,
                            const float* __restrict__ e3,
                            const float* __restrict__ x,
                            const float* __restrict__ ln0w, const float* __restrict__ ln0b,
                            const float* __restrict__ ln1w, const float* __restrict__ ln1b) {
    int warp = threadIdx.x >> 5, lane = threadIdx.x & 31;
    if (blockIdx.x < MTOT/8) {
        int row = blockIdx.x * 8 + warp;
        int sel = mod_idx[row];
        const float* src = ((sel == 2) ? e2 : e3) + (size_t)g_gidx[row] * EE;
        ln_row_warp(src, ln0w, ln0b, g_sn + (size_t)row * EE, lane);
    } else {
        int row = (blockIdx.x - MTOT/8) * 8 + warp;
        ln_row_warp(x + (size_t)row * EE, ln1w, ln1b, g_xn + (size_t)row * EE, lane);
    }
}

__global__ void ln_kernel(const float* __restrict__ src,
                          const float* __restrict__ w,
                          const float* __restrict__ bia,
                          __half* __restrict__ dst) {
    int warp = threadIdx.x >> 5, lane = threadIdx.x & 31;
    int row = blockIdx.x * 8 + warp;
    ln_row_warp(src + (size_t)row * EE, w, bia, dst + (size_t)row * EE, lane);
}

// =====================================================================
// shared mma helpers
// =====================================================================
__device__ __forceinline__ float gelu_exact(float x) {
    return 0.5f * x * (1.0f + erff(x * 0.70710678118654752440f));
}

__device__ __forceinline__ void cp16(uint32_t dst, const void* src) {
    asm volatile("cp.async.cg.shared.global [%0], [%1], 16;" :: "r"(dst), "l"(src));
}
__device__ __forceinline__ void ldsm4(uint32_t* r, uint32_t addr) {
    asm volatile("ldmatrix.sync.aligned.m8n8.x4.shared.b16 {%0,%1,%2,%3}, [%4];"
                 : "=r"(r[0]), "=r"(r[1]), "=r"(r[2]), "=r"(r[3]) : "r"(addr));
}
__device__ __forceinline__ void ldsm2(uint32_t* r, uint32_t addr) {
    asm volatile("ldmatrix.sync.aligned.m8n8.x2.shared.b16 {%0,%1}, [%2];"
                 : "=r"(r[0]), "=r"(r[1]) : "r"(addr));
}
__device__ __forceinline__ void ldsm2t(uint32_t* r, uint32_t addr) {
    asm volatile("ldmatrix.sync.aligned.m8n8.x2.trans.shared.b16 {%0,%1}, [%2];"
                 : "=r"(r[0]), "=r"(r[1]) : "r"(addr));
}
__device__ __forceinline__ void mma16816(float* c, const uint32_t* a, const uint32_t* b) {
    asm volatile(
        "mma.sync.aligned.m16n8k16.row.col.f32.f16.f16.f32 "
        "{%0,%1,%2,%3}, {%4,%5,%6,%7}, {%8,%9}, {%0,%1,%2,%3};"
        : "+f"(c[0]), "+f"(c[1]), "+f"(c[2]), "+f"(c[3])
        : "r"(a[0]), "r"(a[1]), "r"(a[2]), "r"(a[3]), "r"(b[0]), "r"(b[1]));
}

// =====================================================================
// fp16 mma GEMM: C[M,N] = A[M,K] @ W[N,K]^T (+bias, +res/GELU)
// CTA 128(M)x64(N), 4 warps (64x32 tiles), K-chunk 64, 3-stage cp.async,
// single __syncthreads per iter, 3 CTAs/SM.
// =====================================================================
#define NSTAGE 3
#define A_BYTES (128*128)
#define B_BYTES (64*128)
#define STG_BYTES (A_BYTES + B_BYTES)    // 24 KB per stage
#define GEMM_SMEM (NSTAGE*STG_BYTES)     // 73728
#define GTHREADS 128

__device__ __forceinline__ void load_tile(const __half* __restrict__ A,
                                          const __half* __restrict__ W,
                                          int K, int tM, int tN, int k0,
                                          uint32_t sA, int tid) {
    uint32_t sB = sA + A_BYTES;
    // A: 128 rows (1024 cp16), 8 per thread
    #pragma unroll
    for (int j = 0; j < 8; j++) {
        int idx = tid + j * GTHREADS;
        int row = idx >> 3, c = idx & 7;
        uint32_t off = (uint32_t)(row * 128 + ((c ^ (row & 7)) << 4));
        cp16(sA + off, A + (size_t)(tM + row) * K + k0 + c * 8);
    }
    // B: 64 rows (512 cp16), 4 per thread
    #pragma unroll
    for (int j = 0; j < 4; j++) {
        int idx = tid + j * GTHREADS;
        int row = idx >> 3, c = idx & 7;
        uint32_t off = (uint32_t)(row * 128 + ((c ^ (row & 7)) << 4));
        cp16(sB + off, W + (size_t)(tN + row) * K + k0 + c * 8);
    }
}

template <int EPI, typename OT>
__device__ __forceinline__ void gemm_body(const __half* __restrict__ A,
                                          const __half* __restrict__ W,
                                          const float* __restrict__ bias,
                                          const float* __restrict__ R,
                                          OT* __restrict__ C,
                                          int K, int N, int tM, int tN) {
    extern __shared__ __align__(16) char smem[];
    uint32_t smem_b = (uint32_t)__cvta_generic_to_shared(smem);
    int tid = threadIdx.x, wid = tid >> 5, lane = tid & 31;
    int wm = wid & 1, wn = wid >> 1;           // 2x2 warp grid over 128x64
    int gid = lane >> 2, tig = lane & 3;

    const int iters = K >> 6;

    float acc[4][4][4];
    #pragma unroll
    for (int mi = 0; mi < 4; mi++)
        #pragma unroll
        for (int ni = 0; ni < 4; ni++)
            #pragma unroll
            for (int r = 0; r < 4; r++) acc[mi][ni][r] = 0.f;

    #pragma unroll
    for (int s = 0; s < NSTAGE - 1; s++) {
        if (s < iters)
            load_tile(A, W, K, tM, tN, s * 64, smem_b + s * STG_BYTES, tid);
        asm volatile("cp.async.commit_group;" ::: "memory");
    }

    int a_row = wm * 64 + (lane & 15);
    int a_kc  = lane >> 4;
    int b_row = wn * 32 + (lane & 7);
    int b_kc  = (lane >> 3) & 1;

    int stage = 0;
    for (int i = 0; i < iters; i++) {
        asm volatile("cp.async.wait_group %0;" :: "n"(NSTAGE - 2) : "memory");
        __syncthreads();

        int li = i + NSTAGE - 1;
        if (li < iters) {
            int lst = li % NSTAGE;
            load_tile(A, W, K, tM, tN, li * 64, smem_b + lst * STG_BYTES, tid);
        }
        asm volatile("cp.async.commit_group;" ::: "memory");

        uint32_t As = smem_b + stage * STG_BYTES;
        uint32_t Bs = As + A_BYTES;

        #pragma unroll
        for (int ks = 0; ks < 4; ks++) {
            uint32_t a[4][4], b[4][2];
            #pragma unroll
            for (int mi = 0; mi < 4; mi++) {
                int r = a_row + mi * 16;
                int kc = ks * 2 + a_kc;
                ldsm4(a[mi], As + r * 128 + ((kc ^ (r & 7)) << 4));
            }
            #pragma unroll
            for (int ni = 0; ni < 4; ni++) {
                int r = b_row + ni * 8;
                int kc = ks * 2 + b_kc;
                ldsm2(b[ni], Bs + r * 128 + ((kc ^ (r & 7)) << 4));
            }
            #pragma unroll
            for (int mi = 0; mi < 4; mi++)
                #pragma unroll
                for (int ni = 0; ni < 4; ni++)
                    mma16816(acc[mi][ni], a[mi], b[ni]);
        }
        stage = (stage + 1 == NSTAGE) ? 0 : stage + 1;
    }

    #pragma unroll
    for (int mi = 0; mi < 4; mi++) {
        int r0 = tM + wm * 64 + mi * 16 + gid;
        #pragma unroll
        for (int ni = 0; ni < 4; ni++) {
            int c = tN + wn * 32 + ni * 8 + tig * 2;
            float bx = bias[c], by = bias[c + 1];
            float2 v0 = make_float2(acc[mi][ni][0] + bx, acc[mi][ni][1] + by);
            float2 v1 = make_float2(acc[mi][ni][2] + bx, acc[mi][ni][3] + by);
            size_t o0 = (size_t)r0 * N + c;
            size_t o1 = (size_t)(r0 + 8) * N + c;
            if (EPI == 1) {
                float2 rr0 = *(const float2*)(R + o0);
                float2 rr1 = *(const float2*)(R + o1);
                v0.x += rr0.x; v0.y += rr0.y;
                v1.x += rr1.x; v1.y += rr1.y;
                *(float2*)((float*)C + o0) = v0;
                *(float2*)((float*)C + o1) = v1;
            } else {
                if (EPI == 2) {
                    v0.x = gelu_exact(v0.x); v0.y = gelu_exact(v0.y);
                    v1.x = gelu_exact(v1.x); v1.y = gelu_exact(v1.y);
                }
                *(__half2*)((__half*)C + o0) = __floats2half2_rn(v0.x, v0.y);
                *(__half2*)((__half*)C + o1) = __floats2half2_rn(v1.x, v1.y);
            }
        }
    }
}

template <int EPI, typename OT>
__global__ __launch_bounds__(GTHREADS, 3)
void tc_gemm(const __half* __restrict__ A, const __half* __restrict__ W,
             const float* __restrict__ bias, const float* __restrict__ R,
             OT* __restrict__ C, int K, int N) {
    gemm_body<EPI, OT>(A, W, bias, R, C, K, N, blockIdx.y * 128, blockIdx.x * 64);
}

// fused QKV: blockIdx.x in [0,36): 0-11 Q, 12-23 K, 24-35 V (N-tiles of 64)
__global__ __launch_bounds__(GTHREADS, 3)
void qkv_gemm(const float* __restrict__ qb, const float* __restrict__ kb,
              const float* __restrict__ vb) {
    int part = blockIdx.x / 12;
    int bx   = blockIdx.x % 12;
    const __half* A    = (part == 0) ? g_xn : g_sn;
    const __half* W    = (part == 0) ? g_wq : (part == 1) ? g_wk : g_wv;
    const float* bias  = (part == 0) ? qb   : (part == 1) ? kb   : vb;
    __half* C          = (part == 0) ? g_q  : (part == 1) ? g_k  : g_v;
    gemm_body<0, __half>(A, W, bias, nullptr, C, EE, EE, blockIdx.y * 128, bx * 64);
}

// =====================================================================
// tensor-core prefix-masked flash attention
// CTA: 64 queries, 4 warps (16 q-rows each), K-tiles of 64, double buffer.
// =====================================================================
__global__ __launch_bounds__(128)
void attn_kernel() {
    __shared__ __align__(16) __half sQ[64 * 64];
    __shared__ __align__(16) __half sK[2][64 * 64];
    __shared__ __align__(16) __half sV[2][64 * 64];

    int bh = blockIdx.y, b = bh / HH, h = bh - b * HH;
    int qbase = blockIdx.x * 64;
    int tid = threadIdx.x, wid = tid >> 5, lane = tid & 31;
    int gid = lane >> 2, tig = lane & 3;

    uint32_t sQb = (uint32_t)__cvta_generic_to_shared(sQ);
    uint32_t sKb0 = (uint32_t)__cvta_generic_to_shared(sK[0]);
    uint32_t sKb1 = (uint32_t)__cvta_generic_to_shared(sK[1]);
    uint32_t sVb0 = (uint32_t)__cvta_generic_to_shared(sV[0]);
    uint32_t sVb1 = (uint32_t)__cvta_generic_to_shared(sV[1]);

    // load Q tile (64 rows x 64 halves, swizzled)
    {
        const __half* Qg = g_q + ((size_t)(b * LL + qbase)) * EE + h * DD;
        #pragma unroll
        for (int j = 0; j < 4; j++) {
            int idx = tid + j * 128;
            int row = idx >> 3, c = idx & 7;
            cp16(sQb + row * 128 + ((c ^ (row & 7)) << 4), Qg + (size_t)row * EE + c * 8);
        }
    }

    int kmax = g_cnt[b * LL + qbase + 63];
    int nt = (kmax + 63) >> 6;
    int r0g = qbase + wid * 16 + gid;
    int cq0 = g_cnt[b * LL + r0g];
    int cq1 = g_cnt[b * LL + r0g + 8];

    const __half* Kg = g_k + ((size_t)(b * LL)) * EE + h * DD;
    const __half* Vg = g_v + ((size_t)(b * LL)) * EE + h * DD;

    // preload tile 0
    if (nt > 0) {
        #pragma unroll
        for (int j = 0; j < 4; j++) {
            int idx = tid + j * 128;
            int row = idx >> 3, c = idx & 7;
            uint32_t off = row * 128 + ((c ^ (row & 7)) << 4);
            cp16(sKb0 + off, Kg + (size_t)row * EE + c * 8);
            cp16(sVb0 + off, Vg + (size_t)row * EE + c * 8);
        }
    }
    asm volatile("cp.async.commit_group;" ::: "memory");
    asm volatile("cp.async.wait_group 0;" ::: "memory");
    __syncthreads();

    // Q fragments (held in regs for whole kernel)
    uint32_t qf[4][4];
    #pragma unroll
    for (int ks = 0; ks < 4; ks++) {
        int r = wid * 16 + (lane & 15);
        int ch = ks * 2 + (lane >> 4);
        ldsm4(qf[ks], sQb + r * 128 + ((ch ^ (r & 7)) << 4));
    }

    float m0 = -1e30f, m1 = -1e30f, l0 = 0.f, l1 = 0.f;
    float oacc[8][4];
    #pragma unroll
    for (int ni = 0; ni < 8; ni++)
        #pragma unroll
        for (int r = 0; r < 4; r++) oacc[ni][r] = 0.f;

    for (int t = 0; t < nt; t++) {
        uint32_t Ks = (t & 1) ? sKb1 : sKb0;
        uint32_t Vs = (t & 1) ? sVb1 : sVb0;
        if (t + 1 < nt) {
            uint32_t Kn = (t & 1) ? sKb0 : sKb1;
            uint32_t Vn = (t & 1) ? sVb0 : sVb1;
            int koff = (t + 1) * 64;
            #pragma unroll
            for (int j = 0; j < 4; j++) {
                int idx = tid + j * 128;
                int row = idx >> 3, c = idx & 7;
                uint32_t off = row * 128 + ((c ^ (row & 7)) << 4);
                cp16(Kn + off, Kg + (size_t)(koff + row) * EE + c * 8);
                cp16(Vn + off, Vg + (size_t)(koff + row) * EE + c * 8);
            }
        }
        asm volatile("cp.async.commit_group;" ::: "memory");

        // S = Q @ K^T  (fp32 acc)
        float s[8][4];
        #pragma unroll
        for (int ni = 0; ni < 8; ni++)
            #pragma unroll
            for (int r = 0; r < 4; r++) s[ni][r] = 0.f;
        #pragma unroll
        for (int ks = 0; ks < 4; ks++) {
            #pragma unroll
            for (int ni = 0; ni < 8; ni++) {
                uint32_t kb[2];
                int r = ni * 8 + (lane & 7);
                int ch = ks * 2 + ((lane >> 3) & 1);
                ldsm2(kb, Ks + r * 128 + ((ch ^ (r & 7)) << 4));
                mma16816(s[ni], qf[ks], kb);
            }
        }

        // masked online softmax (finite sentinel; no NaNs)
        int k0 = t * 64;
        float rmax0 = -1e30f, rmax1 = -1e30f;
        #pragma unroll
        for (int ni = 0; ni < 8; ni++) {
            int cb = k0 + ni * 8 + tig * 2;
            s[ni][0] = (cb     < cq0) ? s[ni][0] * 0.125f : -1e30f;
            s[ni][1] = (cb + 1 < cq0) ? s[ni][1] * 0.125f : -1e30f;
            s[ni][2] = (cb     < cq1) ? s[ni][2] * 0.125f : -1e30f;
            s[ni][3] = (cb + 1 < cq1) ? s[ni][3] * 0.125f : -1e30f;
            rmax0 = fmaxf(rmax0, fmaxf(s[ni][0], s[ni][1]));
            rmax1 = fmaxf(rmax1, fmaxf(s[ni][2], s[ni][3]));
        }
        rmax0 = fmaxf(rmax0, __shfl_xor_sync(0xffffffffu, rmax0, 1));
        rmax0 = fmaxf(rmax0, __shfl_xor_sync(0xffffffffu, rmax0, 2));
        rmax1 = fmaxf(rmax1, __shfl_xor_sync(0xffffffffu, rmax1, 1));
        rmax1 = fmaxf(rmax1, __shfl_xor_sync(0xffffffffu, rmax1, 2));
        float mn0 = fmaxf(m0, rmax0), mn1 = fmaxf(m1, rmax1);
        float c0 = __expf(m0 - mn0), c1 = __expf(m1 - mn1);
        l0 *= c0; l1 *= c1;
        #pragma unroll
        for (int ni = 0; ni < 8; ni++) {
            oacc[ni][0] *= c0; oacc[ni][1] *= c0;
            oacc[ni][2] *= c1; oacc[ni][3] *= c1;
        }
        uint32_t p16[8][2];
        float ps0 = 0.f, ps1 = 0.f;
        #pragma unroll
        for (int ni = 0; ni < 8; ni++) {
            float p0 = __expf(s[ni][0] - mn0);
            float p1 = __expf(s[ni][1] - mn0);
            float p2 = __expf(s[ni][2] - mn1);
            float p3 = __expf(s[ni][3] - mn1);
            ps0 += p0 + p1; ps1 += p2 + p3;
            p16[ni][0] = h2u(__floats2half2_rn(p0, p1));
            p16[ni][1] = h2u(__floats2half2_rn(p2, p3));
        }
        l0 += ps0; l1 += ps1; m0 = mn0; m1 = mn1;

        // O += P @ V
        #pragma unroll
        for (int ks = 0; ks < 4; ks++) {
            uint32_t pa[4] = { p16[2*ks][0], p16[2*ks][1], p16[2*ks+1][0], p16[2*ks+1][1] };
            #pragma unroll
            for (int ni = 0; ni < 8; ni++) {
                uint32_t vb[2];
                int r = ks * 16 + (lane & 15);
                ldsm2t(vb, Vs + r * 128 + ((ni ^ (r & 7)) << 4));
                mma16816(oacc[ni], pa, vb);
            }
        }

        asm volatile("cp.async.wait_group 0;" ::: "memory");
        __syncthreads();
    }

    // reduce l across quad, write output
    l0 += __shfl_xor_sync(0xffffffffu, l0, 1);
    l0 += __shfl_xor_sync(0xffffffffu, l0, 2);
    l1 += __shfl_xor_sync(0xffffffffu, l1, 1);
    l1 += __shfl_xor_sync(0xffffffffu, l1, 2);
    float invl0 = (cq0 > 0 && l0 > 0.f) ? (1.0f / l0) : 0.f;
    float invl1 = (cq1 > 0 && l1 > 0.f) ? (1.0f / l1) : 0.f;

    __half* Y0 = g_y + ((size_t)(b * LL + r0g)) * EE + h * DD;
    __half* Y1 = g_y + ((size_t)(b * LL + r0g + 8)) * EE + h * DD;
    #pragma unroll
    for (int ni = 0; ni < 8; ni++) {
        int c = ni * 8 + tig * 2;
        *(__half2*)(Y0 + c) = __floats2half2_rn(oacc[ni][0] * invl0, oacc[ni][1] * invl0);
        *(__half2*)(Y1 + c) = __floats2half2_rn(oacc[ni][2] * invl1, oacc[ni][3] * invl1);
    }
}

// ---------------- launch ----------------
extern "C" void kernel_launch(void* const* d_in, const int* in_sizes, int n_in,
                              void* d_out, int out_size) {
    const float* x       = (const float*)d_in[0];
    const float* age     = (const float*)d_in[1];
    const int*   mod_idx = (const int*)  d_in[2];
    const float* mod_age = (const float*)d_in[3];
    const float* e2      = (const float*)d_in[4];
    const float* e3      = (const float*)d_in[5];
    const float* ln0w = (const float*)d_in[6];
    const float* ln0b = (const float*)d_in[7];
    const float* ln1w = (const float*)d_in[8];
    const float* ln1b = (const float*)d_in[9];
    const float* ln2w = (const float*)d_in[10];
    const float* ln2b = (const float*)d_in[11];
    const float* qw = (const float*)d_in[12];
    const float* qb = (const float*)d_in[13];
    const float* kw = (const float*)d_in[14];
    const float* kb = (const float*)d_in[15];
    const float* vw = (const float*)d_in[16];
    const float* vb = (const float*)d_in[17];
    const float* cw = (const float*)d_in[18];
    const float* cb = (const float*)d_in[19];
    const float* fcw = (const float*)d_in[20];
    const float* fcb = (const float*)d_in[21];
    const float* pw  = (const float*)d_in[22];
    const float* pb  = (const float*)d_in[23];
    float* out = (float*)d_out;

    __half *y, *xn2, *hbuf;
    __half *wc, *wfc, *wp;
    float *x1;
    cudaGetSymbolAddress((void**)&y,   g_y);
    cudaGetSymbolAddress((void**)&x1,  g_x1);
    cudaGetSymbolAddress((void**)&xn2, g_xn2);
    cudaGetSymbolAddress((void**)&hbuf, g_h);
    cudaGetSymbolAddress((void**)&wc,  g_wc);
    cudaGetSymbolAddress((void**)&wfc, g_wfc);
    cudaGetSymbolAddress((void**)&wp,  g_wp);

    cudaFuncSetAttribute((const void*)tc_gemm<1, float>,  cudaFuncAttributeMaxDynamicSharedMemorySize, GEMM_SMEM);
    cudaFuncSetAttribute((const void*)tc_gemm<2, __half>, cudaFuncAttributeMaxDynamicSharedMemorySize, GEMM_SMEM);
    cudaFuncSetAttribute((const void*)qkv_gemm,           cudaFuncAttributeMaxDynamicSharedMemorySize, GEMM_SMEM);

    // 0. convert all weights to fp16 in one launch
    {
        const int total = 4*(EE*EE/4) + 2*(FF*EE/4);
        round_w_all<<<(total + 255)/256, 256>>>(qw, kw, vw, cw, fcw, pw);
    }

    // 1. fuse-embed occurrence indices + mask prefix lengths (one launch)
    prep_kernel<<<2*BB, 1024>>>(mod_idx, age, mod_age);

    // 2. LN0(gathered mod embeddings)->sn + LN1(x)->xn  (one launch)
    ln01_kernel<<<2*(MTOT/8), 256>>>(mod_idx, e2, e3, x, ln0w, ln0b, ln1w, ln1b);

    // 3. fused QKV projection (fp16 mma, 128x64 tiles)
    qkv_gemm<<<dim3(36, 32), GTHREADS, GEMM_SMEM>>>(qb, kb, vb);

    // 4. tensor-core prefix-masked flash attention -> y (fp16)
    attn_kernel<<<dim3(LL / 64, BB * HH), 128>>>();

    // 5. out projection + residual -> x1 (fp32)
    tc_gemm<1, float><<<dim3(12, 32), GTHREADS, GEMM_SMEM>>>(y, wc, cb, x, x1, EE, EE);

    // 6. LN2 -> xn2 ; MLP with GELU ; proj + residual -> out
    ln_kernel<<<MTOT/8, 256>>>(x1, ln2w, ln2b, xn2);
    tc_gemm<2, __half><<<dim3(48, 32), GTHREADS, GEMM_SMEM>>>(xn2, wfc, fcb, nullptr, hbuf, EE, FF);
    tc_gemm<1, float><<<dim3(12, 32), GTHREADS, GEMM_SMEM>>>(hbuf, wp, pb, x1, out, FF, EE);
}